// round 13
// baseline (speedup 1.0000x reference)
#include <cuda_runtime.h>
#include <cstdint>
#include <cfloat>

// Problem constants (fixed shapes for MergeNN_38903813767173)
#define B_ 2048
#define N_ 20000
#define D_ 64
#define DY_ 32
#define L_ 100
#define ETA_ 0.01f

#define NP 20224            // 316*64 padded i-extent
#define NCH_TOT 316         // chunks of 64 rows
#define NSLAB_A 9
#define CPS_A 36            // 9*36 = 324 >= 316 ; grid 32*9 = 288 <= 296 (2 CTA/SM wave)
#define NSLAB_C 4
#define CPS_C 79            // 4*79 = 316 ; grid 32*4*2 = 256 <= 296

// Strides ≡ 8 (mod 32) words: the (r0, 2*c0l) lds.64 pattern is conflict-free
#define XS_STR 72           // star/f smem row stride (words)
#define FCS 72              // fcombT smem row stride (words, 64 cols + 8 pad)
#define FC_ROWS 136         // 64+64+1+7 pad
#define SLS 72
#define SL_ROWS 40          // 32+1+7 pad

// ---------------- helpers ----------------------------------------------------
__device__ __forceinline__ uint32_t su32(const void* p) {
    return (uint32_t)__cvta_generic_to_shared(p);
}
#define CPA16(dst, src) \
    asm volatile("cp.async.ca.shared.global [%0], [%1], 16;" :: "r"(dst), "l"(src))
#define CP_COMMIT() asm volatile("cp.async.commit_group;")
#define CP_WAIT0()  asm volatile("cp.async.wait_group 0;" ::: "memory")
#define CP_WAIT1()  asm volatile("cp.async.wait_group 1;" ::: "memory")

__device__ __forceinline__ uint32_t tf(float x) {
    uint32_t r; asm("cvt.rna.tf32.f32 %0, %1;" : "=r"(r) : "f"(x)); return r;
}
__device__ __forceinline__ void mma8(float c[4], const uint32_t a[4], const uint32_t b[2]) {
    asm volatile("mma.sync.aligned.m16n8k8.row.col.f32.tf32.tf32.f32 "
                 "{%0,%1,%2,%3}, {%4,%5,%6,%7}, {%8,%9}, {%0,%1,%2,%3};"
                 : "+f"(c[0]), "+f"(c[1]), "+f"(c[2]), "+f"(c[3])
                 : "r"(a[0]), "r"(a[1]), "r"(a[2]), "r"(a[3]), "r"(b[0]), "r"(b[1]));
}

// ---------------- scratch ----------------------------------------------------
__device__ float g_nx[B_];
__device__ float g_ns[N_];
__device__ float g_nf1[N_];
__device__ float g_nf2[N_];
__device__ int   g_match[B_];

__device__ float g_fcombT[FC_ROWS][NP];   // tf32: rows 0-63 e^{-ns}f1^T, 64-127 e^{-ns}f2^T, 128 e^{-ns}, 129-135 zero
__device__ float g_slbcT[2][SL_ROWS][NP]; // tf32: rows 0-31 e^{-nf}slb^T, 32 e^{-nf}, 33-39 zero

__device__ float g_esum_part[NSLAB_A][B_];
__device__ float g_acc1_part[NSLAB_A][B_][D_];
__device__ float g_acc2_part[NSLAB_A][B_][D_];

__device__ float g_xt1[B_][D_];
__device__ float g_xt2[B_][D_];
__device__ float g_nxt1[B_];
__device__ float g_nxt2[B_];
__device__ int   g_yidx1[B_];
__device__ int   g_yidx2[B_];

__device__ float g_num1_part[NSLAB_C][B_][DY_];
__device__ float g_num2_part[NSLAB_C][B_][DY_];
__device__ float g_den1_part[NSLAB_C][B_];
__device__ float g_den2_part[NSLAB_C][B_];

// ---------------- K0: norms + match init -------------------------------------
__global__ void k_prep(const float* __restrict__ x, const float* __restrict__ star,
                       const float* __restrict__ f1, const float* __restrict__ f2) {
    int gid = blockIdx.x * blockDim.x + threadIdx.x;
    const float* src;
    float* dst;
    if (gid < B_) {
        g_match[gid] = 0x7fffffff;
        src = x + gid * D_;        dst = &g_nx[gid];
    } else if (gid < B_ + N_) {
        int r = gid - B_;          src = star + r * D_; dst = &g_ns[r];
    } else if (gid < B_ + 2 * N_) {
        int r = gid - B_ - N_;     src = f1 + r * D_;   dst = &g_nf1[r];
    } else if (gid < B_ + 3 * N_) {
        int r = gid - B_ - 2 * N_; src = f2 + r * D_;   dst = &g_nf2[r];
    } else return;
    float s = 0.f;
    const float4* p = reinterpret_cast<const float4*>(src);
#pragma unroll
    for (int i = 0; i < 16; i++) {
        float4 v = p[i];
        s += v.x * v.x + v.y * v.y + v.z * v.z + v.w * v.w;
    }
    *dst = s;
}

// ---------------- K0b: g_fcombT (transposed, tf32) ---------------------------
__global__ void k_tfT(const float* __restrict__ f1, const float* __restrict__ f2) {
    __shared__ float ts[32][33];
    int tx = threadIdx.x, ty = threadIdx.y;
    int i0 = blockIdx.x * 32;
    int by = blockIdx.y;
    int i = i0 + tx;
    float sc = (i < N_) ? __expf(-g_ns[i]) : 0.f;
    if (by == 4) {
        for (int r = 128 + ty; r < FC_ROWS; r += 8)
            g_fcombT[r][i] = (r == 128) ? __uint_as_float(tf(sc)) : 0.f;
        return;
    }
    const float* src = (by < 2) ? f1 : f2;
    int d0 = (by & 1) * 32;
    int rowbase = by * 32;
#pragma unroll
    for (int q = 0; q < 4; q++) {
        int r = ty + q * 8;
        ts[r][tx] = src[(long)min(i0 + r, N_ - 1) * 64 + d0 + tx];
    }
    __syncthreads();
#pragma unroll
    for (int q = 0; q < 4; q++) {
        int d = ty + q * 8;
        g_fcombT[rowbase + d][i] = __uint_as_float(tf(ts[tx][d] * sc));
    }
}

// ---------------- K0c: g_slbcT (transposed, tf32) ----------------------------
__global__ void k_tsT(const float* __restrict__ slb) {
    __shared__ float ts[32][33];
    int tx = threadIdx.x, ty = threadIdx.y;
    int i0 = blockIdx.x * 32;
    int br = blockIdx.z;
    int i = i0 + tx;
    float sc = (i < N_) ? __expf(-(br ? g_nf2[i] : g_nf1[i])) : 0.f;
#pragma unroll
    for (int q = 0; q < 4; q++) {
        int r = ty + q * 8;
        ts[r][tx] = slb[(long)min(i0 + r, N_ - 1) * 32 + tx];
    }
    __syncthreads();
#pragma unroll
    for (int q = 0; q < 4; q++) {
        int d = ty + q * 8;
        g_slbcT[br][d][i] = __uint_as_float(tf(ts[tx][d] * sc));
    }
    if (ty == 0) g_slbcT[br][32][i] = __uint_as_float(tf(sc));
    if (33 + ty < SL_ROWS) g_slbcT[br][33 + ty][i] = 0.f;
}

// ---------------- phase A ----------------------------------------------------
// 128 threads (4 warps, JT=64), 2 CTAs/SM. CH=64. FC double, ST single.
// smem (bytes): ST 18432 | FC0 39168 | FC1 39168 | NS 256 = 97024
#define SA_ST 0
#define SA_F0 18432
#define SA_F1 57600
#define SA_NS 96768
#define SA_SIZE 97024

__global__ __launch_bounds__(128, 2)
void k_phaseA(const float* __restrict__ x, const float* __restrict__ star) {
    extern __shared__ char smem[];
    float* STs = (float*)(smem + SA_ST);
    float* fcs[2] = {(float*)(smem + SA_F0), (float*)(smem + SA_F1)};
    float* nsb = (float*)(smem + SA_NS);   // [64]
    const uint32_t STb = su32(STs);
    const uint32_t fbs[2] = {su32(fcs[0]), su32(fcs[1])};

    const int tid = threadIdx.x;
    const int w = tid >> 5, lane = tid & 31;
    const int r0 = lane >> 2, c0l = lane & 3;
    const int jw = w * 16;
    const int j0 = blockIdx.x * 64;
    const int slab = blockIdx.y;
    const int ch0 = slab * CPS_A;
    const int ch1 = min(ch0 + CPS_A, NCH_TOT);
    const int nc = ch1 - ch0;

    // A-fragments straight from global X (once)
    uint32_t aF[8][4];
#pragma unroll
    for (int ks = 0; ks < 8; ks++) {
        uint2 p0 = *(const uint2*)(x + (long)(j0 + jw + r0) * 64 + ks * 8 + 2 * c0l);
        uint2 p1 = *(const uint2*)(x + (long)(j0 + jw + r0 + 8) * 64 + ks * 8 + 2 * c0l);
        aF[ks][0] = p0.x; aF[ks][1] = p1.x; aF[ks][2] = p0.y; aF[ks][3] = p1.y;
    }
    const float nx0 = g_nx[j0 + jw + r0];
    const float nx1 = g_nx[j0 + jw + r0 + 8];

    float acc[17][4];
#pragma unroll
    for (int n = 0; n < 17; n++)
#pragma unroll
        for (int q = 0; q < 4; q++) acc[n][q] = 0.f;

    // prologue: FC(0) in flight
    {
        const int i0p = ch0 * 64;
        for (int idx = tid; idx < FC_ROWS * 16; idx += 128) {
            int r = idx >> 4, g = idx & 15;
            CPA16(fbs[0] + r * (FCS * 4) + g * 16,
                  (const char*)g_fcombT + ((long)r * NP + i0p) * 4 + g * 16);
        }
        CP_COMMIT();
    }

    for (int c = 0; c < nc; c++) {
        const int i0 = (ch0 + c) * 64;
        __syncthreads();   // previous compute done; ST/ns reusable; FC[(c+1)&1] free
        // ST(c) + ns(c)
        for (int idx = tid; idx < 64 * 16; idx += 128) {
            int r = idx >> 4, g = idx & 15;
            long gi = min(i0 + r, N_ - 1);
            CPA16(STb + r * (XS_STR * 4) + g * 16, (const char*)star + gi * 256 + g * 16);
        }
        if (tid < 64) { int gi = i0 + tid; nsb[tid] = (gi < N_) ? g_ns[gi] : 1e30f; }
        CP_COMMIT();
        // prefetch FC(c+1)
        if (c + 1 < nc) {
            const int pb = (c + 1) & 1;
            const int i0n = i0 + 64;
            for (int idx = tid; idx < FC_ROWS * 16; idx += 128) {
                int r = idx >> 4, g = idx & 15;
                CPA16(fbs[pb] + r * (FCS * 4) + g * 16,
                      (const char*)g_fcombT + ((long)r * NP + i0n) * 4 + g * 16);
            }
            CP_COMMIT();
            CP_WAIT1();    // FC(c) + ST(c) done; FC(c+1) in flight
        } else {
            CP_WAIT0();
        }
        __syncthreads();

        const float* FCc = fcs[c & 1];

        // MMA1: S = X . star^T (8 nt tiles)
        float cf[8][4];
#pragma unroll
        for (int n = 0; n < 8; n++)
#pragma unroll
            for (int q = 0; q < 4; q++) cf[n][q] = 0.f;
#pragma unroll
        for (int ks = 0; ks < 8; ks++) {
#pragma unroll
            for (int nt = 0; nt < 8; nt++) {
                uint2 q = *(const uint2*)&STs[(nt * 8 + r0) * XS_STR + ks * 8 + 2 * c0l];
                uint32_t b[2] = {q.x, q.y};
                mma8(cf[nt], aF[ks], b);
            }
        }
        // exp in regs -> fused MMA2
#pragma unroll
        for (int nt = 0; nt < 8; nt++) {
            int ic0 = nt * 8 + 2 * c0l, ic1 = ic0 + 1;
            float ns0 = nsb[ic0], ns1 = nsb[ic1];
            float t00 = 2.f * cf[nt][0] - nx0, t01 = 2.f * cf[nt][1] - nx0;
            float t10 = 2.f * cf[nt][2] - nx1, t11 = 2.f * cf[nt][3] - nx1;
            if (t00 >= ns0) atomicMin(&g_match[j0 + jw + r0], i0 + ic0);
            if (t01 >= ns1) atomicMin(&g_match[j0 + jw + r0], i0 + ic1);
            if (t10 >= ns0) atomicMin(&g_match[j0 + jw + r0 + 8], i0 + ic0);
            if (t11 >= ns1) atomicMin(&g_match[j0 + jw + r0 + 8], i0 + ic1);
            uint32_t a2[4];
            a2[0] = __float_as_uint(__expf(t00));
            a2[1] = __float_as_uint(__expf(t10));
            a2[2] = __float_as_uint(__expf(t01));
            a2[3] = __float_as_uint(__expf(t11));
#pragma unroll
            for (int nt2 = 0; nt2 < 17; nt2++) {
                uint2 q = *(const uint2*)&FCc[(nt2 * 8 + r0) * FCS + nt * 8 + 2 * c0l];
                uint32_t b[2] = {q.x, q.y};
                mma8(acc[nt2], a2, b);
            }
        }
    }

    // writeback
    const int jr0 = j0 + jw + r0, jr1 = jr0 + 8;
#pragma unroll
    for (int nt = 0; nt < 17; nt++) {
        int n = nt * 8 + 2 * c0l;
        if (n < 64) {
            *(float2*)&g_acc1_part[slab][jr0][n] = make_float2(acc[nt][0], acc[nt][1]);
            *(float2*)&g_acc1_part[slab][jr1][n] = make_float2(acc[nt][2], acc[nt][3]);
        } else if (n < 128) {
            *(float2*)&g_acc2_part[slab][jr0][n - 64] = make_float2(acc[nt][0], acc[nt][1]);
            *(float2*)&g_acc2_part[slab][jr1][n - 64] = make_float2(acc[nt][2], acc[nt][3]);
        } else if (n == 128) {
            g_esum_part[slab][jr0] = acc[nt][0];
            g_esum_part[slab][jr1] = acc[nt][2];
        }
    }
}

// ---------------- K2: middle — xt, y = xt@W+b, argmin label ------------------
__global__ __launch_bounds__(128)
void k_mid(const float* __restrict__ f1, const float* __restrict__ f2,
           const float* __restrict__ W1, const float* __restrict__ b1,
           const float* __restrict__ W2, const float* __restrict__ b2,
           const float* __restrict__ u1, const float* __restrict__ u2) {
    int j = blockIdx.x;
    int t = threadIdx.x;

    __shared__ float xts[D_];
    __shared__ float ys[DY_];
    __shared__ float esum_s;
    __shared__ float ny_s;
    __shared__ float redv[128];
    __shared__ int   redi[128];

    int  mi = g_match[j];
    bool hm = (mi != 0x7fffffff);
    if (t == 0) {
        float s = 0.f;
        for (int k = 0; k < NSLAB_A; k++) s += g_esum_part[k][j];
        esum_s = s;
    }
    __syncthreads();

    for (int br = 0; br < 2; br++) {
        const float* f  = br ? f2 : f1;
        const float* W  = br ? W2 : W1;
        const float* bb = br ? b2 : b1;
        const float* u  = br ? u2 : u1;

        if (t < D_) {
            float a = 0.f;
            if (br) { for (int k = 0; k < NSLAB_A; k++) a += g_acc2_part[k][j][t]; }
            else    { for (int k = 0; k < NSLAB_A; k++) a += g_acc1_part[k][j][t]; }
            float v = hm ? f[mi * D_ + t] : a / esum_s;
            xts[t] = v;
            if (br) g_xt2[j][t] = v; else g_xt1[j][t] = v;
        }
        __syncthreads();
        if (t == 0) {
            float s = 0.f;
            for (int d = 0; d < D_; d++) s += xts[d] * xts[d];
            if (br) g_nxt2[j] = s; else g_nxt1[j] = s;
        }
        if (t < DY_) {
            float a = bb[t];
            for (int d = 0; d < D_; d++) a += xts[d] * W[d * DY_ + t];
            ys[t] = a;
        }
        __syncthreads();
        if (t == 0) {
            float s = 0.f;
            for (int dy = 0; dy < DY_; dy++) s += ys[dy] * ys[dy];
            ny_s = s;
        }
        __syncthreads();

        float v = FLT_MAX;
        int   vi = 0x7fffffff;
        if (t < L_) {
            float nu = 0.f, dot = 0.f;
            for (int dy = 0; dy < DY_; dy++) {
                float uu = u[t * DY_ + dy];
                nu += uu * uu;
                dot += uu * ys[dy];
            }
            v = fmaxf(ny_s + nu - 2.f * dot, 0.f);
            vi = t;
        }
        redv[t] = v; redi[t] = vi;
        __syncthreads();
        for (int off = 64; off > 0; off >>= 1) {
            if (t < off) {
                float v2 = redv[t + off]; int i2 = redi[t + off];
                if (v2 < redv[t] || (v2 == redv[t] && i2 < redi[t])) {
                    redv[t] = v2; redi[t] = i2;
                }
            }
            __syncthreads();
        }
        if (t == 0) { if (br) g_yidx2[j] = redi[0]; else g_yidx1[j] = redi[0]; }
        __syncthreads();
    }
}

// ---------------- phase C ----------------------------------------------------
// 128 threads (4 warps, JT=64), 2 CTAs/SM. CH=64. F and SL both double-buffered.
// smem (bytes): F0 18432 | F1 18432 | SL0 11520 | SL1 11520 | MT 25856 | LI 512 | YJ 256
#define SC_F0 0
#define SC_F1 18432
#define SC_S0 36864
#define SC_S1 48384
#define SC_MT 59904
#define SC_LI 85760
#define SC_YJ 86272
#define SC_SIZE 86528

__global__ __launch_bounds__(128, 2)
void k_phaseC(const float* __restrict__ f1, const float* __restrict__ f2,
              const float* __restrict__ ld1, const float* __restrict__ ld2,
              const int* __restrict__ li1, const int* __restrict__ li2) {
    extern __shared__ char smem[];
    float* fsb[2] = {(float*)(smem + SC_F0), (float*)(smem + SC_F1)};
    float* slb2[2] = {(float*)(smem + SC_S0), (float*)(smem + SC_S1)};
    float* mt  = (float*)(smem + SC_MT);    // [64][101]
    int*   lib = (int*)(smem + SC_LI);      // [2][64]
    int*   yjs = (int*)(smem + SC_YJ);      // [64]
    const uint32_t fbs[2] = {su32(fsb[0]), su32(fsb[1])};
    const uint32_t sbs[2] = {su32(slb2[0]), su32(slb2[1])};

    const int tid = threadIdx.x;
    const int w = tid >> 5, lane = tid & 31;
    const int r0 = lane >> 2, c0l = lane & 3;
    const int jw = w * 16;
    const int j0 = blockIdx.x * 64;
    const int slab = blockIdx.y;
    const int br = blockIdx.z;
    const int ch0 = slab * CPS_C;
    const int ch1 = min(ch0 + CPS_C, NCH_TOT);
    const int nc = ch1 - ch0;

    const float* f  = br ? f2 : f1;
    const float* ld = br ? ld2 : ld1;
    const int*   li = br ? li2 : li1;
    const float (*xt)[D_] = br ? g_xt2 : g_xt1;
    const float* nxt = br ? g_nxt2 : g_nxt1;
    const int*   yix = br ? g_yidx2 : g_yidx1;
    float (*nump)[B_][DY_] = br ? g_num2_part : g_num1_part;
    float (*denp)[B_]      = br ? g_den2_part : g_den1_part;

    // A-fragments straight from global xt (once)
    uint32_t aF[8][4];
#pragma unroll
    for (int ks = 0; ks < 8; ks++) {
        uint2 p0 = *(const uint2*)&xt[j0 + jw + r0][ks * 8 + 2 * c0l];
        uint2 p1 = *(const uint2*)&xt[j0 + jw + r0 + 8][ks * 8 + 2 * c0l];
        aF[ks][0] = p0.x; aF[ks][1] = p1.x; aF[ks][2] = p0.y; aF[ks][3] = p1.y;
    }
    const float nxt0 = nxt[j0 + jw + r0];
    const float nxt1 = nxt[j0 + jw + r0 + 8];
    if (tid < 64) yjs[tid] = yix[j0 + tid];
    __syncthreads();
    for (int idx = tid; idx < 64 * L_; idx += 128) {
        int j = idx / L_, l = idx - j * L_;
        mt[j * 101 + l] = __expf(-ETA_ * ld[l * L_ + yjs[j]]);
    }

    float acc[5][4];
#pragma unroll
    for (int n = 0; n < 5; n++)
#pragma unroll
        for (int q = 0; q < 4; q++) acc[n][q] = 0.f;

    // prologue: group(0) in flight
    {
        const int i0p = ch0 * 64;
        for (int idx = tid; idx < 64 * 16; idx += 128) {
            int r = idx >> 4, g = idx & 15;
            long gi = min(i0p + r, N_ - 1);
            CPA16(fbs[0] + r * (XS_STR * 4) + g * 16, (const char*)f + gi * 256 + g * 16);
        }
        for (int idx = tid; idx < SL_ROWS * 16; idx += 128) {
            int r = idx >> 4, g = idx & 15;
            CPA16(sbs[0] + r * (SLS * 4) + g * 16,
                  (const char*)&g_slbcT[br][0][0] + ((long)r * NP + i0p) * 4 + g * 16);
        }
        if (tid < 64) lib[tid] = li[min(i0p + tid, N_ - 1)];
        CP_COMMIT();
    }

    for (int c = 0; c < nc; c++) {
        const int i0 = (ch0 + c) * 64;
        __syncthreads();   // compute(c-1) done; buffers [(c+1)&1] free
        if (c + 1 < nc) {
            const int pb = (c + 1) & 1;
            const int i0n = i0 + 64;
            for (int idx = tid; idx < 64 * 16; idx += 128) {
                int r = idx >> 4, g = idx & 15;
                long gi = min(i0n + r, N_ - 1);
                CPA16(fbs[pb] + r * (XS_STR * 4) + g * 16, (const char*)f + gi * 256 + g * 16);
            }
            for (int idx = tid; idx < SL_ROWS * 16; idx += 128) {
                int r = idx >> 4, g = idx & 15;
                CPA16(sbs[pb] + r * (SLS * 4) + g * 16,
                      (const char*)&g_slbcT[br][0][0] + ((long)r * NP + i0n) * 4 + g * 16);
            }
            if (tid < 64) lib[pb * 64 + tid] = li[min(i0n + tid, N_ - 1)];
            CP_COMMIT();
            CP_WAIT1();    // group(c) done; group(c+1) flying
        } else {
            CP_WAIT0();
        }
        __syncthreads();

        const float* Fs  = fsb[c & 1];
        const float* SLc = slb2[c & 1];
        const int*   lic = lib + (c & 1) * 64;

        float cf[8][4];
#pragma unroll
        for (int n = 0; n < 8; n++)
#pragma unroll
            for (int q = 0; q < 4; q++) cf[n][q] = 0.f;
#pragma unroll
        for (int ks = 0; ks < 8; ks++) {
#pragma unroll
            for (int nt = 0; nt < 8; nt++) {
                uint2 q = *(const uint2*)&Fs[(nt * 8 + r0) * XS_STR + ks * 8 + 2 * c0l];
                uint32_t b[2] = {q.x, q.y};
                mma8(cf[nt], aF[ks], b);
            }
        }
#pragma unroll
        for (int nt = 0; nt < 8; nt++) {
            int ic0 = nt * 8 + 2 * c0l, ic1 = ic0 + 1;
            int l0 = lic[ic0], l1 = lic[ic1];
            float m00 = mt[(jw + r0) * 101 + l0], m01 = mt[(jw + r0) * 101 + l1];
            float m10 = mt[(jw + r0 + 8) * 101 + l0], m11 = mt[(jw + r0 + 8) * 101 + l1];
            uint32_t a2[4];
            a2[0] = __float_as_uint(__expf(2.f * cf[nt][0] - nxt0) * m00);
            a2[1] = __float_as_uint(__expf(2.f * cf[nt][2] - nxt1) * m10);
            a2[2] = __float_as_uint(__expf(2.f * cf[nt][1] - nxt0) * m01);
            a2[3] = __float_as_uint(__expf(2.f * cf[nt][3] - nxt1) * m11);
#pragma unroll
            for (int nt2 = 0; nt2 < 5; nt2++) {
                uint2 q = *(const uint2*)&SLc[(nt2 * 8 + r0) * SLS + nt * 8 + 2 * c0l];
                uint32_t b[2] = {q.x, q.y};
                mma8(acc[nt2], a2, b);
            }
        }
    }

    const int jr0 = j0 + jw + r0, jr1 = jr0 + 8;
#pragma unroll
    for (int nt = 0; nt < 5; nt++) {
        int n = nt * 8 + 2 * c0l;
        if (n < 32) {
            *(float2*)&nump[slab][jr0][n] = make_float2(acc[nt][0], acc[nt][1]);
            *(float2*)&nump[slab][jr1][n] = make_float2(acc[nt][2], acc[nt][3]);
        } else if (n == 32) {
            denp[slab][jr0] = acc[nt][0];
            denp[slab][jr1] = acc[nt][2];
        }
    }
}

// ---------------- K4: reduce partials ----------------------------------------
__global__ void k_out(float* __restrict__ out) {
    int gid = blockIdx.x * blockDim.x + threadIdx.x;
    if (gid >= B_ * DY_) return;
    int j = gid >> 5, dy = gid & 31;
    float n1 = 0.f, d1 = 0.f, n2 = 0.f, d2 = 0.f;
    for (int s = 0; s < NSLAB_C; s++) {
        n1 += g_num1_part[s][j][dy];
        d1 += g_den1_part[s][j];
        n2 += g_num2_part[s][j][dy];
        d2 += g_den2_part[s][j];
    }
    out[gid] = 0.5f * (n1 / d1 + n2 / d2);
}

// ---------------- launch -----------------------------------------------------
extern "C" void kernel_launch(void* const* d_in, const int* in_sizes, int n_in,
                              void* d_out, int out_size) {
    const float* x    = (const float*)d_in[0];
    const float* star = (const float*)d_in[1];
    const float* slb  = (const float*)d_in[2];
    const float* f1   = (const float*)d_in[3];
    const float* f2   = (const float*)d_in[4];
    const float* u1   = (const float*)d_in[5];
    const float* u2   = (const float*)d_in[6];
    const float* ld1  = (const float*)d_in[7];
    const float* ld2  = (const float*)d_in[8];
    const float* W1   = (const float*)d_in[9];
    const float* b1   = (const float*)d_in[10];
    const float* W2   = (const float*)d_in[11];
    const float* b2   = (const float*)d_in[12];
    const int*   li1  = (const int*)d_in[13];
    const int*   li2  = (const int*)d_in[14];
    float* out = (float*)d_out;

    cudaFuncSetAttribute(k_phaseA, cudaFuncAttributeMaxDynamicSharedMemorySize, SA_SIZE);
    cudaFuncSetAttribute(k_phaseC, cudaFuncAttributeMaxDynamicSharedMemorySize, SC_SIZE);

    k_prep<<<(B_ + 3 * N_ + 255) / 256, 256>>>(x, star, f1, f2);
    k_tfT<<<dim3(NP / 32, 5), dim3(32, 8)>>>(f1, f2);
    k_tsT<<<dim3(NP / 32, 1, 2), dim3(32, 8)>>>(slb);
    k_phaseA<<<dim3(32, NSLAB_A), 128, SA_SIZE>>>(x, star);
    k_mid<<<B_, 128>>>(f1, f2, W1, b1, W2, b2, u1, u2);
    k_phaseC<<<dim3(32, NSLAB_C, 2), 128, SC_SIZE>>>(f1, f2, ld1, ld2, li1, li2);
    k_out<<<(B_ * DY_ + 255) / 256, 256>>>(out);
}

// round 14
// speedup vs baseline: 1.1704x; 1.1704x over previous
#include <cuda_runtime.h>
#include <cstdint>
#include <cfloat>

// Problem constants (fixed shapes for MergeNN_38903813767173)
#define B_ 2048
#define N_ 20000
#define D_ 64
#define DY_ 32
#define L_ 100
#define ETA_ 0.01f

#define NP 20224            // 158*128 padded i-extent
#define NCH_TOT 158
#define NSLAB_A 9
#define CPS_A 18            // grid 32*9 = 288 <= 296 (2 CTA/SM, one wave)
#define NSLAB_C 4
#define CPS_C 40            // grid 32*4*2 = 256 <= 296

// Strides ≡ 8 (mod 32) words: the (r0, 2*c0l) lds.64 pattern is conflict-free
#define XS_STR 72           // star/f smem row stride (words)
#define FCS 136             // fcombT smem row stride (words)
#define FC_ROWS 136         // 64+64+1+7 pad
#define SLS 136
#define SL_ROWS 40          // 32+1+7 pad

// ---------------- helpers ----------------------------------------------------
__device__ __forceinline__ uint32_t su32(const void* p) {
    return (uint32_t)__cvta_generic_to_shared(p);
}
#define CPA16(dst, src) \
    asm volatile("cp.async.ca.shared.global [%0], [%1], 16;" :: "r"(dst), "l"(src))
#define CP_COMMIT() asm volatile("cp.async.commit_group;")
#define CP_WAIT0()  asm volatile("cp.async.wait_group 0;" ::: "memory")
#define CP_WAIT1()  asm volatile("cp.async.wait_group 1;" ::: "memory")

__device__ __forceinline__ uint32_t tf(float x) {
    uint32_t r; asm("cvt.rna.tf32.f32 %0, %1;" : "=r"(r) : "f"(x)); return r;
}
__device__ __forceinline__ void mma8(float c[4], const uint32_t a[4], const uint32_t b[2]) {
    asm volatile("mma.sync.aligned.m16n8k8.row.col.f32.tf32.tf32.f32 "
                 "{%0,%1,%2,%3}, {%4,%5,%6,%7}, {%8,%9}, {%0,%1,%2,%3};"
                 : "+f"(c[0]), "+f"(c[1]), "+f"(c[2]), "+f"(c[3])
                 : "r"(a[0]), "r"(a[1]), "r"(a[2]), "r"(a[3]), "r"(b[0]), "r"(b[1]));
}

// ---------------- scratch ----------------------------------------------------
__device__ float g_nx[B_];
__device__ float g_ns[N_];
__device__ float g_nf1[N_];
__device__ float g_nf2[N_];
__device__ int   g_match[B_];

__device__ float g_fcombT[FC_ROWS][NP];   // tf32: rows 0-63 e^{-ns}f1^T, 64-127 e^{-ns}f2^T, 128 e^{-ns}, 129-135 zero
__device__ float g_slbcT[2][SL_ROWS][NP]; // tf32: rows 0-31 e^{-nf}slb^T, 32 e^{-nf}, 33-39 zero

__device__ float g_esum_part[NSLAB_A][B_];
__device__ float g_acc1_part[NSLAB_A][B_][D_];
__device__ float g_acc2_part[NSLAB_A][B_][D_];

__device__ float g_xt1[B_][D_];
__device__ float g_xt2[B_][D_];
__device__ float g_nxt1[B_];
__device__ float g_nxt2[B_];
__device__ int   g_yidx1[B_];
__device__ int   g_yidx2[B_];

__device__ float g_num1_part[NSLAB_C][B_][DY_];
__device__ float g_num2_part[NSLAB_C][B_][DY_];
__device__ float g_den1_part[NSLAB_C][B_];
__device__ float g_den2_part[NSLAB_C][B_];

// ---------------- K0: norms + match init -------------------------------------
__global__ void k_prep(const float* __restrict__ x, const float* __restrict__ star,
                       const float* __restrict__ f1, const float* __restrict__ f2) {
    int gid = blockIdx.x * blockDim.x + threadIdx.x;
    const float* src;
    float* dst;
    if (gid < B_) {
        g_match[gid] = 0x7fffffff;
        src = x + gid * D_;        dst = &g_nx[gid];
    } else if (gid < B_ + N_) {
        int r = gid - B_;          src = star + r * D_; dst = &g_ns[r];
    } else if (gid < B_ + 2 * N_) {
        int r = gid - B_ - N_;     src = f1 + r * D_;   dst = &g_nf1[r];
    } else if (gid < B_ + 3 * N_) {
        int r = gid - B_ - 2 * N_; src = f2 + r * D_;   dst = &g_nf2[r];
    } else return;
    float s = 0.f;
    const float4* p = reinterpret_cast<const float4*>(src);
#pragma unroll
    for (int i = 0; i < 16; i++) {
        float4 v = p[i];
        s += v.x * v.x + v.y * v.y + v.z * v.z + v.w * v.w;
    }
    *dst = s;
}

// ---------------- K0b: g_fcombT (transposed, tf32) ---------------------------
__global__ void k_tfT(const float* __restrict__ f1, const float* __restrict__ f2) {
    __shared__ float ts[32][33];
    int tx = threadIdx.x, ty = threadIdx.y;
    int i0 = blockIdx.x * 32;
    int by = blockIdx.y;
    int i = i0 + tx;
    float sc = (i < N_) ? __expf(-g_ns[i]) : 0.f;
    if (by == 4) {
        for (int r = 128 + ty; r < FC_ROWS; r += 8)
            g_fcombT[r][i] = (r == 128) ? __uint_as_float(tf(sc)) : 0.f;
        return;
    }
    const float* src = (by < 2) ? f1 : f2;
    int d0 = (by & 1) * 32;
    int rowbase = by * 32;
#pragma unroll
    for (int q = 0; q < 4; q++) {
        int r = ty + q * 8;
        ts[r][tx] = src[(long)min(i0 + r, N_ - 1) * 64 + d0 + tx];
    }
    __syncthreads();
#pragma unroll
    for (int q = 0; q < 4; q++) {
        int d = ty + q * 8;
        g_fcombT[rowbase + d][i] = __uint_as_float(tf(ts[tx][d] * sc));
    }
}

// ---------------- K0c: g_slbcT (transposed, tf32) ----------------------------
__global__ void k_tsT(const float* __restrict__ slb) {
    __shared__ float ts[32][33];
    int tx = threadIdx.x, ty = threadIdx.y;
    int i0 = blockIdx.x * 32;
    int br = blockIdx.z;
    int i = i0 + tx;
    float sc = (i < N_) ? __expf(-(br ? g_nf2[i] : g_nf1[i])) : 0.f;
#pragma unroll
    for (int q = 0; q < 4; q++) {
        int r = ty + q * 8;
        ts[r][tx] = slb[(long)min(i0 + r, N_ - 1) * 32 + tx];
    }
    __syncthreads();
#pragma unroll
    for (int q = 0; q < 4; q++) {
        int d = ty + q * 8;
        g_slbcT[br][d][i] = __uint_as_float(tf(ts[tx][d] * sc));
    }
    if (ty == 0) g_slbcT[br][32][i] = __uint_as_float(tf(sc));
    if (33 + ty < SL_ROWS) g_slbcT[br][33 + ty][i] = 0.f;
}

// ---------------- phase A ----------------------------------------------------
// 128 threads (4 warps, JT=64), 2 CTAs/SM, CH=128, split-group async pipeline.
// smem (bytes): ST 36864 | FC 73984 | NS 1024 = 111872
#define SA_ST 0
#define SA_FC 36864
#define SA_NS 110848
#define SA_SIZE 111872

__global__ __launch_bounds__(128, 2)
void k_phaseA(const float* __restrict__ x, const float* __restrict__ star) {
    extern __shared__ char smem[];
    float* STs = (float*)(smem + SA_ST);
    float* FCs = (float*)(smem + SA_FC);
    float* nsb = (float*)(smem + SA_NS);   // [2][128]
    const uint32_t STb = su32(STs), FCb = su32(FCs);

    const int tid = threadIdx.x;
    const int w = tid >> 5, lane = tid & 31;
    const int r0 = lane >> 2, c0l = lane & 3;
    const int jw = w * 16;
    const int j0 = blockIdx.x * 64;
    const int slab = blockIdx.y;
    const int ch0 = slab * CPS_A;
    const int ch1 = min(ch0 + CPS_A, NCH_TOT);
    const int nc = ch1 - ch0;

    // prologue: issue ST(0)+ns(0) [grp], FC(0) [grp]; overlap with aF loads
    {
        const int i0p = ch0 * 128;
        for (int idx = tid; idx < 128 * 16; idx += 128) {
            int r = idx >> 4, g = idx & 15;
            long gi = min(i0p + r, N_ - 1);
            CPA16(STb + r * (XS_STR * 4) + g * 16, (const char*)star + gi * 256 + g * 16);
        }
        { int gi = i0p + tid; nsb[tid] = (gi < N_) ? g_ns[gi] : 1e30f; }
        CP_COMMIT();
        for (int idx = tid; idx < FC_ROWS * 32; idx += 128) {
            int r = idx >> 5, g = idx & 31;
            CPA16(FCb + r * (FCS * 4) + g * 16,
                  (const char*)g_fcombT + ((long)r * NP + i0p) * 4 + g * 16);
        }
        CP_COMMIT();
    }

    // A-fragments straight from global X (fly during prologue loads)
    uint32_t aF[8][4];
#pragma unroll
    for (int ks = 0; ks < 8; ks++) {
        uint2 p0 = *(const uint2*)(x + (long)(j0 + jw + r0) * 64 + ks * 8 + 2 * c0l);
        uint2 p1 = *(const uint2*)(x + (long)(j0 + jw + r0 + 8) * 64 + ks * 8 + 2 * c0l);
        aF[ks][0] = p0.x; aF[ks][1] = p1.x; aF[ks][2] = p0.y; aF[ks][3] = p1.y;
    }
    const float nx0 = g_nx[j0 + jw + r0];
    const float nx1 = g_nx[j0 + jw + r0 + 8];

    CP_WAIT0();
    __syncthreads();

    float acc[17][4];
#pragma unroll
    for (int n = 0; n < 17; n++)
#pragma unroll
        for (int q = 0; q < 4; q++) acc[n][q] = 0.f;

    bool fc_pending = false;
    for (int c = 0; c < nc; c++) {
        const int i0 = (ch0 + c) * 128;
        const bool more = (c + 1 < nc);
        const float* nsc = nsb + (c & 1) * 128;

        // ---- half0: MMA1 ----
        float cf[8][4];
#pragma unroll
        for (int n = 0; n < 8; n++)
#pragma unroll
            for (int q = 0; q < 4; q++) cf[n][q] = 0.f;
#pragma unroll
        for (int ks = 0; ks < 8; ks++) {
#pragma unroll
            for (int nt = 0; nt < 8; nt++) {
                uint2 q = *(const uint2*)&STs[(nt * 8 + r0) * XS_STR + ks * 8 + 2 * c0l];
                uint32_t b[2] = {q.x, q.y};
                mma8(cf[nt], aF[ks], b);
            }
        }
        // FC(c) may still be in flight (issued at end of previous iteration)
        if (fc_pending) { CP_WAIT0(); __syncthreads(); fc_pending = false; }
        // ---- half0: exp + MMA2 ----
#pragma unroll
        for (int nt = 0; nt < 8; nt++) {
            int ic0 = nt * 8 + 2 * c0l, ic1 = ic0 + 1;
            float ns0 = nsc[ic0], ns1 = nsc[ic1];
            float t00 = 2.f * cf[nt][0] - nx0, t01 = 2.f * cf[nt][1] - nx0;
            float t10 = 2.f * cf[nt][2] - nx1, t11 = 2.f * cf[nt][3] - nx1;
            if (t00 >= ns0) atomicMin(&g_match[j0 + jw + r0], i0 + ic0);
            if (t01 >= ns1) atomicMin(&g_match[j0 + jw + r0], i0 + ic1);
            if (t10 >= ns0) atomicMin(&g_match[j0 + jw + r0 + 8], i0 + ic0);
            if (t11 >= ns1) atomicMin(&g_match[j0 + jw + r0 + 8], i0 + ic1);
            uint32_t a2[4];
            a2[0] = __float_as_uint(__expf(t00));
            a2[1] = __float_as_uint(__expf(t10));
            a2[2] = __float_as_uint(__expf(t01));
            a2[3] = __float_as_uint(__expf(t11));
#pragma unroll
            for (int nt2 = 0; nt2 < 17; nt2++) {
                uint2 q = *(const uint2*)&FCs[(nt2 * 8 + r0) * FCS + nt * 8 + 2 * c0l];
                uint32_t b[2] = {q.x, q.y};
                mma8(acc[nt2], a2, b);
            }
        }

        // ---- half1: MMA1 (last ST reads) ----
#pragma unroll
        for (int n = 0; n < 8; n++)
#pragma unroll
            for (int q = 0; q < 4; q++) cf[n][q] = 0.f;
#pragma unroll
        for (int ks = 0; ks < 8; ks++) {
#pragma unroll
            for (int nt = 0; nt < 8; nt++) {
                uint2 q = *(const uint2*)&STs[((8 + nt) * 8 + r0) * XS_STR + ks * 8 + 2 * c0l];
                uint32_t b[2] = {q.x, q.y};
                mma8(cf[nt], aF[ks], b);
            }
        }
        // issue ST(c+1) now — flies under half1 exp+MMA2
        if (more) {
            __syncthreads();   // all warps done reading STs/nsb[c]
            const int i0n = i0 + 128;
            for (int idx = tid; idx < 128 * 16; idx += 128) {
                int r = idx >> 4, g = idx & 15;
                long gi = min(i0n + r, N_ - 1);
                CPA16(STb + r * (XS_STR * 4) + g * 16, (const char*)star + gi * 256 + g * 16);
            }
            { int gi = i0n + tid; nsb[((c + 1) & 1) * 128 + tid] = (gi < N_) ? g_ns[gi] : 1e30f; }
            CP_COMMIT();
        }
        // ---- half1: exp + MMA2 (last FC reads) ----
#pragma unroll
        for (int nt = 0; nt < 8; nt++) {
            int ic0 = (8 + nt) * 8 + 2 * c0l, ic1 = ic0 + 1;
            float ns0 = nsc[ic0], ns1 = nsc[ic1];
            float t00 = 2.f * cf[nt][0] - nx0, t01 = 2.f * cf[nt][1] - nx0;
            float t10 = 2.f * cf[nt][2] - nx1, t11 = 2.f * cf[nt][3] - nx1;
            if (t00 >= ns0) atomicMin(&g_match[j0 + jw + r0], i0 + ic0);
            if (t01 >= ns1) atomicMin(&g_match[j0 + jw + r0], i0 + ic1);
            if (t10 >= ns0) atomicMin(&g_match[j0 + jw + r0 + 8], i0 + ic0);
            if (t11 >= ns1) atomicMin(&g_match[j0 + jw + r0 + 8], i0 + ic1);
            uint32_t a2[4];
            a2[0] = __float_as_uint(__expf(t00));
            a2[1] = __float_as_uint(__expf(t10));
            a2[2] = __float_as_uint(__expf(t01));
            a2[3] = __float_as_uint(__expf(t11));
#pragma unroll
            for (int nt2 = 0; nt2 < 17; nt2++) {
                uint2 q = *(const uint2*)&FCs[(nt2 * 8 + r0) * FCS + (8 + nt) * 8 + 2 * c0l];
                uint32_t b[2] = {q.x, q.y};
                mma8(acc[nt2], a2, b);
            }
        }
        if (more) {
            __syncthreads();   // all warps done reading FCs
            const int i0n = i0 + 128;
            for (int idx = tid; idx < FC_ROWS * 32; idx += 128) {
                int r = idx >> 5, g = idx & 31;
                CPA16(FCb + r * (FCS * 4) + g * 16,
                      (const char*)g_fcombT + ((long)r * NP + i0n) * 4 + g * 16);
            }
            CP_COMMIT();
            CP_WAIT1();        // ST(c+1) done; FC(c+1) still flying
            __syncthreads();
            fc_pending = true;
        }
    }

    // writeback
    const int jr0 = j0 + jw + r0, jr1 = jr0 + 8;
#pragma unroll
    for (int nt = 0; nt < 17; nt++) {
        int n = nt * 8 + 2 * c0l;
        if (n < 64) {
            *(float2*)&g_acc1_part[slab][jr0][n] = make_float2(acc[nt][0], acc[nt][1]);
            *(float2*)&g_acc1_part[slab][jr1][n] = make_float2(acc[nt][2], acc[nt][3]);
        } else if (n < 128) {
            *(float2*)&g_acc2_part[slab][jr0][n - 64] = make_float2(acc[nt][0], acc[nt][1]);
            *(float2*)&g_acc2_part[slab][jr1][n - 64] = make_float2(acc[nt][2], acc[nt][3]);
        } else if (n == 128) {
            g_esum_part[slab][jr0] = acc[nt][0];
            g_esum_part[slab][jr1] = acc[nt][2];
        }
    }
}

// ---------------- K2: middle — xt, y = xt@W+b, argmin label ------------------
__global__ __launch_bounds__(128)
void k_mid(const float* __restrict__ f1, const float* __restrict__ f2,
           const float* __restrict__ W1, const float* __restrict__ b1,
           const float* __restrict__ W2, const float* __restrict__ b2,
           const float* __restrict__ u1, const float* __restrict__ u2) {
    int j = blockIdx.x;
    int t = threadIdx.x;

    __shared__ float xts[D_];
    __shared__ float ys[DY_];
    __shared__ float esum_s;
    __shared__ float ny_s;
    __shared__ float redv[128];
    __shared__ int   redi[128];

    int  mi = g_match[j];
    bool hm = (mi != 0x7fffffff);
    if (t == 0) {
        float s = 0.f;
        for (int k = 0; k < NSLAB_A; k++) s += g_esum_part[k][j];
        esum_s = s;
    }
    __syncthreads();

    for (int br = 0; br < 2; br++) {
        const float* f  = br ? f2 : f1;
        const float* W  = br ? W2 : W1;
        const float* bb = br ? b2 : b1;
        const float* u  = br ? u2 : u1;

        if (t < D_) {
            float a = 0.f;
            if (br) { for (int k = 0; k < NSLAB_A; k++) a += g_acc2_part[k][j][t]; }
            else    { for (int k = 0; k < NSLAB_A; k++) a += g_acc1_part[k][j][t]; }
            float v = hm ? f[mi * D_ + t] : a / esum_s;
            xts[t] = v;
            if (br) g_xt2[j][t] = v; else g_xt1[j][t] = v;
        }
        __syncthreads();
        if (t == 0) {
            float s = 0.f;
            for (int d = 0; d < D_; d++) s += xts[d] * xts[d];
            if (br) g_nxt2[j] = s; else g_nxt1[j] = s;
        }
        if (t < DY_) {
            float a = bb[t];
            for (int d = 0; d < D_; d++) a += xts[d] * W[d * DY_ + t];
            ys[t] = a;
        }
        __syncthreads();
        if (t == 0) {
            float s = 0.f;
            for (int dy = 0; dy < DY_; dy++) s += ys[dy] * ys[dy];
            ny_s = s;
        }
        __syncthreads();

        float v = FLT_MAX;
        int   vi = 0x7fffffff;
        if (t < L_) {
            float nu = 0.f, dot = 0.f;
            for (int dy = 0; dy < DY_; dy++) {
                float uu = u[t * DY_ + dy];
                nu += uu * uu;
                dot += uu * ys[dy];
            }
            v = fmaxf(ny_s + nu - 2.f * dot, 0.f);
            vi = t;
        }
        redv[t] = v; redi[t] = vi;
        __syncthreads();
        for (int off = 64; off > 0; off >>= 1) {
            if (t < off) {
                float v2 = redv[t + off]; int i2 = redi[t + off];
                if (v2 < redv[t] || (v2 == redv[t] && i2 < redi[t])) {
                    redv[t] = v2; redi[t] = i2;
                }
            }
            __syncthreads();
        }
        if (t == 0) { if (br) g_yidx2[j] = redi[0]; else g_yidx1[j] = redi[0]; }
        __syncthreads();
    }
}

// ---------------- phase C ----------------------------------------------------
// 128 threads (4 warps, JT=64), 2 CTAs/SM, CH=128, split-group async pipeline.
// smem (bytes): F 36864 | SL 21760 | MT 25856 | LI 1024 | YJ 256 = 85760
#define SC_F  0
#define SC_SL 36864
#define SC_MT 58624
#define SC_LI 84480
#define SC_YJ 85504
#define SC_SIZE 85760

__global__ __launch_bounds__(128, 2)
void k_phaseC(const float* __restrict__ f1, const float* __restrict__ f2,
              const float* __restrict__ ld1, const float* __restrict__ ld2,
              const int* __restrict__ li1, const int* __restrict__ li2) {
    extern __shared__ char smem[];
    float* Fs  = (float*)(smem + SC_F);
    float* SLs = (float*)(smem + SC_SL);
    float* mt  = (float*)(smem + SC_MT);    // [64][101]
    int*   lib = (int*)(smem + SC_LI);      // [2][128]
    int*   yjs = (int*)(smem + SC_YJ);      // [64]
    const uint32_t Fb = su32(Fs), SLb = su32(SLs);

    const int tid = threadIdx.x;
    const int w = tid >> 5, lane = tid & 31;
    const int r0 = lane >> 2, c0l = lane & 3;
    const int jw = w * 16;
    const int j0 = blockIdx.x * 64;
    const int slab = blockIdx.y;
    const int br = blockIdx.z;
    const int ch0 = slab * CPS_C;
    const int ch1 = min(ch0 + CPS_C, NCH_TOT);
    const int nc = ch1 - ch0;

    const float* f  = br ? f2 : f1;
    const float* ld = br ? ld2 : ld1;
    const int*   li = br ? li2 : li1;
    const float (*xt)[D_] = br ? g_xt2 : g_xt1;
    const float* nxt = br ? g_nxt2 : g_nxt1;
    const int*   yix = br ? g_yidx2 : g_yidx1;
    float (*nump)[B_][DY_] = br ? g_num2_part : g_num1_part;
    float (*denp)[B_]      = br ? g_den2_part : g_den1_part;

    // prologue: issue F(0)+lib(0) [grp], SL(0) [grp]; overlap with aF + mt build
    {
        const int i0p = ch0 * 128;
        for (int idx = tid; idx < 128 * 16; idx += 128) {
            int r = idx >> 4, g = idx & 15;
            long gi = min(i0p + r, N_ - 1);
            CPA16(Fb + r * (XS_STR * 4) + g * 16, (const char*)f + gi * 256 + g * 16);
        }
        lib[tid] = li[min(i0p + tid, N_ - 1)];
        CP_COMMIT();
        for (int idx = tid; idx < SL_ROWS * 32; idx += 128) {
            int r = idx >> 5, g = idx & 31;
            CPA16(SLb + r * (SLS * 4) + g * 16,
                  (const char*)&g_slbcT[br][0][0] + ((long)r * NP + i0p) * 4 + g * 16);
        }
        CP_COMMIT();
    }

    uint32_t aF[8][4];
#pragma unroll
    for (int ks = 0; ks < 8; ks++) {
        uint2 p0 = *(const uint2*)&xt[j0 + jw + r0][ks * 8 + 2 * c0l];
        uint2 p1 = *(const uint2*)&xt[j0 + jw + r0 + 8][ks * 8 + 2 * c0l];
        aF[ks][0] = p0.x; aF[ks][1] = p1.x; aF[ks][2] = p0.y; aF[ks][3] = p1.y;
    }
    const float nxt0 = nxt[j0 + jw + r0];
    const float nxt1 = nxt[j0 + jw + r0 + 8];
    if (tid < 64) yjs[tid] = yix[j0 + tid];
    __syncthreads();
    // mt[j][l] = exp(-eta * ld[l][yidx_j]) — overlaps prologue cp.async
    for (int idx = tid; idx < 64 * L_; idx += 128) {
        int j = idx / L_, l = idx - j * L_;
        mt[j * 101 + l] = __expf(-ETA_ * ld[l * L_ + yjs[j]]);
    }
    CP_WAIT0();
    __syncthreads();

    float acc[5][4];
#pragma unroll
    for (int n = 0; n < 5; n++)
#pragma unroll
        for (int q = 0; q < 4; q++) acc[n][q] = 0.f;

    bool sl_pending = false;
    for (int c = 0; c < nc; c++) {
        const bool more = (c + 1 < nc);
        const int* lic = lib + (c & 1) * 128;

        // ---- half0: MMA1 ----
        float cf[8][4];
#pragma unroll
        for (int n = 0; n < 8; n++)
#pragma unroll
            for (int q = 0; q < 4; q++) cf[n][q] = 0.f;
#pragma unroll
        for (int ks = 0; ks < 8; ks++) {
#pragma unroll
            for (int nt = 0; nt < 8; nt++) {
                uint2 q = *(const uint2*)&Fs[(nt * 8 + r0) * XS_STR + ks * 8 + 2 * c0l];
                uint32_t b[2] = {q.x, q.y};
                mma8(cf[nt], aF[ks], b);
            }
        }
        if (sl_pending) { CP_WAIT0(); __syncthreads(); sl_pending = false; }
        // ---- half0: exp + MMA2 ----
#pragma unroll
        for (int nt = 0; nt < 8; nt++) {
            int ic0 = nt * 8 + 2 * c0l, ic1 = ic0 + 1;
            int l0 = lic[ic0], l1 = lic[ic1];
            float m00 = mt[(jw + r0) * 101 + l0], m01 = mt[(jw + r0) * 101 + l1];
            float m10 = mt[(jw + r0 + 8) * 101 + l0], m11 = mt[(jw + r0 + 8) * 101 + l1];
            uint32_t a2[4];
            a2[0] = __float_as_uint(__expf(2.f * cf[nt][0] - nxt0) * m00);
            a2[1] = __float_as_uint(__expf(2.f * cf[nt][2] - nxt1) * m10);
            a2[2] = __float_as_uint(__expf(2.f * cf[nt][1] - nxt0) * m01);
            a2[3] = __float_as_uint(__expf(2.f * cf[nt][3] - nxt1) * m11);
#pragma unroll
            for (int nt2 = 0; nt2 < 5; nt2++) {
                uint2 q = *(const uint2*)&SLs[(nt2 * 8 + r0) * SLS + nt * 8 + 2 * c0l];
                uint32_t b[2] = {q.x, q.y};
                mma8(acc[nt2], a2, b);
            }
        }

        // ---- half1: MMA1 (last F reads) ----
#pragma unroll
        for (int n = 0; n < 8; n++)
#pragma unroll
            for (int q = 0; q < 4; q++) cf[n][q] = 0.f;
#pragma unroll
        for (int ks = 0; ks < 8; ks++) {
#pragma unroll
            for (int nt = 0; nt < 8; nt++) {
                uint2 q = *(const uint2*)&Fs[((8 + nt) * 8 + r0) * XS_STR + ks * 8 + 2 * c0l];
                uint32_t b[2] = {q.x, q.y};
                mma8(cf[nt], aF[ks], b);
            }
        }
        if (more) {
            __syncthreads();   // F/lib[c] reads done... lib[c] still read below — lib is parity-buffered, writes go to lib[(c+1)&1]
            const int i0n = (ch0 + c + 1) * 128;
            for (int idx = tid; idx < 128 * 16; idx += 128) {
                int r = idx >> 4, g = idx & 15;
                long gi = min(i0n + r, N_ - 1);
                CPA16(Fb + r * (XS_STR * 4) + g * 16, (const char*)f + gi * 256 + g * 16);
            }
            lib[((c + 1) & 1) * 128 + tid] = li[min(i0n + tid, N_ - 1)];
            CP_COMMIT();
        }
        // ---- half1: exp + MMA2 (last SL reads) ----
#pragma unroll
        for (int nt = 0; nt < 8; nt++) {
            int ic0 = (8 + nt) * 8 + 2 * c0l, ic1 = ic0 + 1;
            int l0 = lic[ic0], l1 = lic[ic1];
            float m00 = mt[(jw + r0) * 101 + l0], m01 = mt[(jw + r0) * 101 + l1];
            float m10 = mt[(jw + r0 + 8) * 101 + l0], m11 = mt[(jw + r0 + 8) * 101 + l1];
            uint32_t a2[4];
            a2[0] = __float_as_uint(__expf(2.f * cf[nt][0] - nxt0) * m00);
            a2[1] = __float_as_uint(__expf(2.f * cf[nt][2] - nxt1) * m10);
            a2[2] = __float_as_uint(__expf(2.f * cf[nt][1] - nxt0) * m01);
            a2[3] = __float_as_uint(__expf(2.f * cf[nt][3] - nxt1) * m11);
#pragma unroll
            for (int nt2 = 0; nt2 < 5; nt2++) {
                uint2 q = *(const uint2*)&SLs[(nt2 * 8 + r0) * SLS + (8 + nt) * 8 + 2 * c0l];
                uint32_t b[2] = {q.x, q.y};
                mma8(acc[nt2], a2, b);
            }
        }
        if (more) {
            __syncthreads();   // SL reads done
            const int i0n = (ch0 + c + 1) * 128;
            for (int idx = tid; idx < SL_ROWS * 32; idx += 128) {
                int r = idx >> 5, g = idx & 31;
                CPA16(SLb + r * (SLS * 4) + g * 16,
                      (const char*)&g_slbcT[br][0][0] + ((long)r * NP + i0n) * 4 + g * 16);
            }
            CP_COMMIT();
            CP_WAIT1();        // F(c+1) done; SL(c+1) still flying
            __syncthreads();
            sl_pending = true;
        }
    }

    const int jr0 = j0 + jw + r0, jr1 = jr0 + 8;
#pragma unroll
    for (int nt = 0; nt < 5; nt++) {
        int n = nt * 8 + 2 * c0l;
        if (n < 32) {
            *(float2*)&nump[slab][jr0][n] = make_float2(acc[nt][0], acc[nt][1]);
            *(float2*)&nump[slab][jr1][n] = make_float2(acc[nt][2], acc[nt][3]);
        } else if (n == 32) {
            denp[slab][jr0] = acc[nt][0];
            denp[slab][jr1] = acc[nt][2];
        }
    }
}

// ---------------- K4: reduce partials ----------------------------------------
__global__ void k_out(float* __restrict__ out) {
    int gid = blockIdx.x * blockDim.x + threadIdx.x;
    if (gid >= B_ * DY_) return;
    int j = gid >> 5, dy = gid & 31;
    float n1 = 0.f, d1 = 0.f, n2 = 0.f, d2 = 0.f;
    for (int s = 0; s < NSLAB_C; s++) {
        n1 += g_num1_part[s][j][dy];
        d1 += g_den1_part[s][j];
        n2 += g_num2_part[s][j][dy];
        d2 += g_den2_part[s][j];
    }
    out[gid] = 0.5f * (n1 / d1 + n2 / d2);
}

// ---------------- launch -----------------------------------------------------
extern "C" void kernel_launch(void* const* d_in, const int* in_sizes, int n_in,
                              void* d_out, int out_size) {
    const float* x    = (const float*)d_in[0];
    const float* star = (const float*)d_in[1];
    const float* slb  = (const float*)d_in[2];
    const float* f1   = (const float*)d_in[3];
    const float* f2   = (const float*)d_in[4];
    const float* u1   = (const float*)d_in[5];
    const float* u2   = (const float*)d_in[6];
    const float* ld1  = (const float*)d_in[7];
    const float* ld2  = (const float*)d_in[8];
    const float* W1   = (const float*)d_in[9];
    const float* b1   = (const float*)d_in[10];
    const float* W2   = (const float*)d_in[11];
    const float* b2   = (const float*)d_in[12];
    const int*   li1  = (const int*)d_in[13];
    const int*   li2  = (const int*)d_in[14];
    float* out = (float*)d_out;

    cudaFuncSetAttribute(k_phaseA, cudaFuncAttributeMaxDynamicSharedMemorySize, SA_SIZE);
    cudaFuncSetAttribute(k_phaseC, cudaFuncAttributeMaxDynamicSharedMemorySize, SC_SIZE);

    k_prep<<<(B_ + 3 * N_ + 255) / 256, 256>>>(x, star, f1, f2);
    k_tfT<<<dim3(NP / 32, 5), dim3(32, 8)>>>(f1, f2);
    k_tsT<<<dim3(NP / 32, 1, 2), dim3(32, 8)>>>(slb);
    k_phaseA<<<dim3(32, NSLAB_A), 128, SA_SIZE>>>(x, star);
    k_mid<<<B_, 128>>>(f1, f2, W1, b1, W2, b2, u1, u2);
    k_phaseC<<<dim3(32, NSLAB_C, 2), 128, SC_SIZE>>>(f1, f2, ld1, ld2, li1, li2);
    k_out<<<(B_ * DY_ + 255) / 256, 256>>>(out);
}

// round 15
// speedup vs baseline: 1.5502x; 1.3245x over previous
#include <cuda_runtime.h>
#include <cuda_fp16.h>
#include <cstdint>
#include <cfloat>

// Problem constants (fixed shapes for MergeNN_38903813767173)
#define B_ 2048
#define N_ 20000
#define D_ 64
#define DY_ 32
#define L_ 100
#define ETA_ 0.01f

#define NP 20224            // 158*128 padded i-extent
#define NCH_TOT 158
#define NSLAB_A 9
#define CPS_A 18            // grid 32*9 = 288 <= 296 (2 CTA/SM, one wave)
#define NSLAB_C 4
#define CPS_C 40            // grid 32*4*2 = 256 <= 296

#define ST_STR 40           // fp16 star/f smem row stride in u32 (160B; 40%32=8 conflict-free)
#define FC_STR 72           // fp16 fcomb smem row stride in u32 (288B; 72%32=8)
#define SL_STR 72
#define FC_ROWS 136         // 64+64+1+7 pad
#define SL_ROWS 40          // 32+1+7 pad

// ---------------- helpers ----------------------------------------------------
__device__ __forceinline__ uint32_t su32(const void* p) {
    return (uint32_t)__cvta_generic_to_shared(p);
}
#define CPA16(dst, src) \
    asm volatile("cp.async.ca.shared.global [%0], [%1], 16;" :: "r"(dst), "l"(src))
#define CP_COMMIT() asm volatile("cp.async.commit_group;")
#define CP_WAIT0()  asm volatile("cp.async.wait_group 0;" ::: "memory")

__device__ __forceinline__ uint32_t packh(float lo, float hi) {
    __half2 h = __floats2half2_rn(lo, hi);
    return *(uint32_t*)&h;
}
// fp16 m16n8k16: K=16 per instruction, fp32 accumulate
__device__ __forceinline__ void mma16(float c[4], const uint32_t a[4], const uint32_t b[2]) {
    asm volatile("mma.sync.aligned.m16n8k16.row.col.f32.f16.f16.f32 "
                 "{%0,%1,%2,%3}, {%4,%5,%6,%7}, {%8,%9}, {%0,%1,%2,%3};"
                 : "+f"(c[0]), "+f"(c[1]), "+f"(c[2]), "+f"(c[3])
                 : "r"(a[0]), "r"(a[1]), "r"(a[2]), "r"(a[3]), "r"(b[0]), "r"(b[1]));
}

// ---------------- scratch ----------------------------------------------------
__device__ float g_nx[B_];
__device__ float g_ns[N_];
__device__ float g_nf1[N_];
__device__ float g_nf2[N_];
__device__ int   g_match[B_];

__device__ __half g_xh[B_][D_];        // x, fp16, natural d
__device__ __half g_sth[NP][D_];       // star, fp16, d-pairs slot-permuted
__device__ __half g_f1h[NP][D_];       // f1, fp16, d-pairs slot-permuted
__device__ __half g_f2h[NP][D_];
__device__ __half g_fch[FC_ROWS][NP];  // e^{-ns}[f1|f2|1|0], fp16, i-pairs slot-permuted
__device__ __half g_slh[2][SL_ROWS][NP]; // e^{-nf}[slb|1|0], fp16, i-pairs slot-permuted
__device__ __half g_xth[2][B_][D_];    // xt, fp16, natural d (written by k_mid)

__device__ float g_esum_part[NSLAB_A][B_];
__device__ float g_acc1_part[NSLAB_A][B_][D_];
__device__ float g_acc2_part[NSLAB_A][B_][D_];

__device__ float g_xt1[B_][D_];
__device__ float g_xt2[B_][D_];
__device__ float g_nxt1[B_];
__device__ float g_nxt2[B_];
__device__ int   g_yidx1[B_];
__device__ int   g_yidx2[B_];

__device__ float g_num1_part[NSLAB_C][B_][DY_];
__device__ float g_num2_part[NSLAB_C][B_][DY_];
__device__ float g_den1_part[NSLAB_C][B_];
__device__ float g_den2_part[NSLAB_C][B_];

// ---------------- K0: norms + match init -------------------------------------
__global__ void k_prep(const float* __restrict__ x, const float* __restrict__ star,
                       const float* __restrict__ f1, const float* __restrict__ f2) {
    int gid = blockIdx.x * blockDim.x + threadIdx.x;
    const float* src;
    float* dst;
    if (gid < B_) {
        g_match[gid] = 0x7fffffff;
        src = x + gid * D_;        dst = &g_nx[gid];
    } else if (gid < B_ + N_) {
        int r = gid - B_;          src = star + r * D_; dst = &g_ns[r];
    } else if (gid < B_ + 2 * N_) {
        int r = gid - B_ - N_;     src = f1 + r * D_;   dst = &g_nf1[r];
    } else if (gid < B_ + 3 * N_) {
        int r = gid - B_ - 2 * N_; src = f2 + r * D_;   dst = &g_nf2[r];
    } else return;
    float s = 0.f;
    const float4* p = reinterpret_cast<const float4*>(src);
#pragma unroll
    for (int i = 0; i < 16; i++) {
        float4 v = p[i];
        s += v.x * v.x + v.y * v.y + v.z * v.z + v.w * v.w;
    }
    *dst = s;
}

// slot s within an 8-slot group holds physical pair (s even ? s/2 : s/2+4)
__device__ __forceinline__ int physpos(int stor) {
    int g = stor & ~15, s = (stor >> 1) & 7, e = stor & 1;
    int p = (s & 1) ? (s >> 1) + 4 : (s >> 1);
    return g + 2 * p + e;
}

// ---------------- K0b: fp16 x (natural) + star/f1/f2 (permuted) --------------
__global__ void k_h1(const float* __restrict__ x, const float* __restrict__ star,
                     const float* __restrict__ f1, const float* __restrict__ f2) {
    int gid = blockIdx.x * blockDim.x + threadIdx.x;
    if (gid < B_ * D_) {
        ((__half*)g_xh)[gid] = __float2half(x[gid]);
        return;
    }
    gid -= B_ * D_;
    if (gid >= 3 * NP * D_) return;
    int which = gid / (NP * D_);
    int rem = gid - which * (NP * D_);
    int i = rem >> 6, d = rem & 63;     // d = storage index
    int dp = physpos(d);
    float v = 0.f;
    if (i < N_) {
        const float* src = (which == 0) ? star : ((which == 1) ? f1 : f2);
        v = src[(long)i * D_ + dp];
    }
    __half hv = __float2half(v);
    if (which == 0) g_sth[i][d] = hv;
    else if (which == 1) g_f1h[i][d] = hv;
    else g_f2h[i][d] = hv;
}

// ---------------- K0c: fp16 fcomb (i-permuted) -------------------------------
__global__ void k_h2(const float* __restrict__ f1, const float* __restrict__ f2) {
    int gid = blockIdx.x * blockDim.x + threadIdx.x;
    if (gid >= FC_ROWS * NP) return;
    int r = gid / NP, ic = gid - r * NP;  // ic = storage col
    int i = physpos(ic);
    float v = 0.f;
    if (i < N_) {
        float sc = __expf(-g_ns[i]);
        if (r < 64)       v = f1[(long)i * D_ + r] * sc;
        else if (r < 128) v = f2[(long)i * D_ + r - 64] * sc;
        else if (r == 128) v = sc;
    }
    g_fch[r][ic] = __float2half(v);
}

// ---------------- K0d: fp16 slbcomb (i-permuted) -----------------------------
__global__ void k_h3(const float* __restrict__ slb) {
    int gid = blockIdx.x * blockDim.x + threadIdx.x;
    if (gid >= 2 * SL_ROWS * NP) return;
    int br = gid / (SL_ROWS * NP);
    int rem = gid - br * (SL_ROWS * NP);
    int r = rem / NP, ic = rem - r * NP;
    int i = physpos(ic);
    float v = 0.f;
    if (i < N_) {
        float sc = __expf(-(br ? g_nf2[i] : g_nf1[i]));
        if (r < 32)       v = slb[(long)i * DY_ + r] * sc;
        else if (r == 32) v = sc;
    }
    g_slh[br][r][ic] = __float2half(v);
}

// ---------------- phase A ----------------------------------------------------
// 128 threads (4 warps, JT=64), 2 CTAs/SM, CH=128, fp16 operands.
// smem (bytes): ST 20480 | FC 39168 | NS 512 = 60160
#define SA_ST 0
#define SA_FC 20480
#define SA_NS 59648
#define SA_SIZE 60160

__global__ __launch_bounds__(128, 2)
void k_phaseA() {
    extern __shared__ char smem[];
    uint32_t* STu = (uint32_t*)(smem + SA_ST);
    uint32_t* FCu = (uint32_t*)(smem + SA_FC);
    float* nsb = (float*)(smem + SA_NS);   // [128]
    const uint32_t STb = su32(STu), FCb = su32(FCu);

    const int tid = threadIdx.x;
    const int w = tid >> 5, lane = tid & 31;
    const int r0 = lane >> 2, c0l = lane & 3;
    const int jw = w * 16;
    const int j0 = blockIdx.x * 64;
    const int slab = blockIdx.y;
    const int ch0 = slab * CPS_A;
    const int ch1 = min(ch0 + CPS_A, NCH_TOT);
    const int nc = ch1 - ch0;

    // A-fragments from g_xh (natural pairs: pair p at u32 slot p)
    uint32_t aF[4][4];
    {
        const uint32_t* xr0 = (const uint32_t*)&g_xh[j0 + jw + r0][0];
        const uint32_t* xr1 = (const uint32_t*)&g_xh[j0 + jw + r0 + 8][0];
#pragma unroll
        for (int ks = 0; ks < 4; ks++) {
            aF[ks][0] = xr0[ks * 8 + c0l];
            aF[ks][1] = xr1[ks * 8 + c0l];
            aF[ks][2] = xr0[ks * 8 + c0l + 4];
            aF[ks][3] = xr1[ks * 8 + c0l + 4];
        }
    }
    const float nx0 = g_nx[j0 + jw + r0];
    const float nx1 = g_nx[j0 + jw + r0 + 8];

    // chunk 0 loads
    {
        const int i0p = ch0 * 128;
        for (int idx = tid; idx < 128 * 8; idx += 128) {
            int r = idx >> 3, g = idx & 7;
            long gi = min(i0p + r, N_ - 1);
            CPA16(STb + r * 160 + g * 16, (const char*)&g_sth[gi][0] + g * 16);
        }
        for (int idx = tid; idx < FC_ROWS * 16; idx += 128) {
            int r = idx >> 4, g = idx & 15;
            CPA16(FCb + r * 288 + g * 16, (const char*)&g_fch[r][i0p] + g * 16);
        }
        { int gi = i0p + tid; nsb[tid] = (gi < N_) ? g_ns[gi] : 1e30f; }
        CP_COMMIT(); CP_WAIT0();
        __syncthreads();
    }

    float acc[17][4];
#pragma unroll
    for (int n = 0; n < 17; n++)
#pragma unroll
        for (int q = 0; q < 4; q++) acc[n][q] = 0.f;

    for (int c = 0; c < nc; c++) {
        const int i0 = (ch0 + c) * 128;

        // fused per kc (16 i's): MMA1 (nt=2kc,2kc+1) -> exp -> MMA2(kc)
#pragma unroll
        for (int kc = 0; kc < 8; kc++) {
            float cf0[4] = {0.f, 0.f, 0.f, 0.f};
            float cf1[4] = {0.f, 0.f, 0.f, 0.f};
#pragma unroll
            for (int ks = 0; ks < 4; ks++) {
                uint2 q0 = *(const uint2*)&STu[((2 * kc) * 8 + r0) * ST_STR + ks * 8 + 2 * c0l];
                uint32_t b0[2] = {q0.x, q0.y};
                mma16(cf0, aF[ks], b0);
                uint2 q1 = *(const uint2*)&STu[((2 * kc + 1) * 8 + r0) * ST_STR + ks * 8 + 2 * c0l];
                uint32_t b1[2] = {q1.x, q1.y};
                mma16(cf1, aF[ks], b1);
            }
            const int ic0 = kc * 16 + 2 * c0l, ic1 = ic0 + 1;
            const int jc0 = ic0 + 8, jc1 = ic1 + 8;
            float ns0 = nsb[ic0], ns1 = nsb[ic1];
            float ns2 = nsb[jc0], ns3 = nsb[jc1];
            float t00 = 2.f * cf0[0] - nx0, t01 = 2.f * cf0[1] - nx0;
            float t10 = 2.f * cf0[2] - nx1, t11 = 2.f * cf0[3] - nx1;
            float t20 = 2.f * cf1[0] - nx0, t21 = 2.f * cf1[1] - nx0;
            float t30 = 2.f * cf1[2] - nx1, t31 = 2.f * cf1[3] - nx1;
            if (t00 >= ns0) atomicMin(&g_match[j0 + jw + r0], i0 + ic0);
            if (t01 >= ns1) atomicMin(&g_match[j0 + jw + r0], i0 + ic1);
            if (t10 >= ns0) atomicMin(&g_match[j0 + jw + r0 + 8], i0 + ic0);
            if (t11 >= ns1) atomicMin(&g_match[j0 + jw + r0 + 8], i0 + ic1);
            if (t20 >= ns2) atomicMin(&g_match[j0 + jw + r0], i0 + jc0);
            if (t21 >= ns3) atomicMin(&g_match[j0 + jw + r0], i0 + jc1);
            if (t30 >= ns2) atomicMin(&g_match[j0 + jw + r0 + 8], i0 + jc0);
            if (t31 >= ns3) atomicMin(&g_match[j0 + jw + r0 + 8], i0 + jc1);
            uint32_t a2[4];
            a2[0] = packh(__expf(t00), __expf(t01));
            a2[1] = packh(__expf(t10), __expf(t11));
            a2[2] = packh(__expf(t20), __expf(t21));
            a2[3] = packh(__expf(t30), __expf(t31));
#pragma unroll
            for (int nt2 = 0; nt2 < 17; nt2++) {
                uint2 q = *(const uint2*)&FCu[(nt2 * 8 + r0) * FC_STR + kc * 8 + 2 * c0l];
                uint32_t b[2] = {q.x, q.y};
                mma16(acc[nt2], a2, b);
            }
        }

        // reload (cross-CTA overlap hides this)
        if (c + 1 < nc) {
            __syncthreads();
            const int i0n = i0 + 128;
            for (int idx = tid; idx < 128 * 8; idx += 128) {
                int r = idx >> 3, g = idx & 7;
                long gi = min(i0n + r, N_ - 1);
                CPA16(STb + r * 160 + g * 16, (const char*)&g_sth[gi][0] + g * 16);
            }
            for (int idx = tid; idx < FC_ROWS * 16; idx += 128) {
                int r = idx >> 4, g = idx & 15;
                CPA16(FCb + r * 288 + g * 16, (const char*)&g_fch[r][i0n] + g * 16);
            }
            { int gi = i0n + tid; nsb[tid] = (gi < N_) ? g_ns[gi] : 1e30f; }
            CP_COMMIT(); CP_WAIT0();
            __syncthreads();
        }
    }

    // writeback
    const int jr0 = j0 + jw + r0, jr1 = jr0 + 8;
#pragma unroll
    for (int nt = 0; nt < 17; nt++) {
        int n = nt * 8 + 2 * c0l;
        if (n < 64) {
            *(float2*)&g_acc1_part[slab][jr0][n] = make_float2(acc[nt][0], acc[nt][1]);
            *(float2*)&g_acc1_part[slab][jr1][n] = make_float2(acc[nt][2], acc[nt][3]);
        } else if (n < 128) {
            *(float2*)&g_acc2_part[slab][jr0][n - 64] = make_float2(acc[nt][0], acc[nt][1]);
            *(float2*)&g_acc2_part[slab][jr1][n - 64] = make_float2(acc[nt][2], acc[nt][3]);
        } else if (n == 128) {
            g_esum_part[slab][jr0] = acc[nt][0];
            g_esum_part[slab][jr1] = acc[nt][2];
        }
    }
}

// ---------------- K2: middle — xt, y = xt@W+b, argmin label ------------------
__global__ __launch_bounds__(128)
void k_mid(const float* __restrict__ f1, const float* __restrict__ f2,
           const float* __restrict__ W1, const float* __restrict__ b1,
           const float* __restrict__ W2, const float* __restrict__ b2,
           const float* __restrict__ u1, const float* __restrict__ u2) {
    int j = blockIdx.x;
    int t = threadIdx.x;

    __shared__ float xts[D_];
    __shared__ float ys[DY_];
    __shared__ float esum_s;
    __shared__ float ny_s;
    __shared__ float redv[128];
    __shared__ int   redi[128];

    int  mi = g_match[j];
    bool hm = (mi != 0x7fffffff);
    if (t == 0) {
        float s = 0.f;
        for (int k = 0; k < NSLAB_A; k++) s += g_esum_part[k][j];
        esum_s = s;
    }
    __syncthreads();

    for (int br = 0; br < 2; br++) {
        const float* f  = br ? f2 : f1;
        const float* W  = br ? W2 : W1;
        const float* bb = br ? b2 : b1;
        const float* u  = br ? u2 : u1;

        if (t < D_) {
            float a = 0.f;
            if (br) { for (int k = 0; k < NSLAB_A; k++) a += g_acc2_part[k][j][t]; }
            else    { for (int k = 0; k < NSLAB_A; k++) a += g_acc1_part[k][j][t]; }
            float v = hm ? f[mi * D_ + t] : a / esum_s;
            xts[t] = v;
            if (br) g_xt2[j][t] = v; else g_xt1[j][t] = v;
            g_xth[br][j][t] = __float2half(v);
        }
        __syncthreads();
        if (t == 0) {
            float s = 0.f;
            for (int d = 0; d < D_; d++) s += xts[d] * xts[d];
            if (br) g_nxt2[j] = s; else g_nxt1[j] = s;
        }
        if (t < DY_) {
            float a = bb[t];
            for (int d = 0; d < D_; d++) a += xts[d] * W[d * DY_ + t];
            ys[t] = a;
        }
        __syncthreads();
        if (t == 0) {
            float s = 0.f;
            for (int dy = 0; dy < DY_; dy++) s += ys[dy] * ys[dy];
            ny_s = s;
        }
        __syncthreads();

        float v = FLT_MAX;
        int   vi = 0x7fffffff;
        if (t < L_) {
            float nu = 0.f, dot = 0.f;
            for (int dy = 0; dy < DY_; dy++) {
                float uu = u[t * DY_ + dy];
                nu += uu * uu;
                dot += uu * ys[dy];
            }
            v = fmaxf(ny_s + nu - 2.f * dot, 0.f);
            vi = t;
        }
        redv[t] = v; redi[t] = vi;
        __syncthreads();
        for (int off = 64; off > 0; off >>= 1) {
            if (t < off) {
                float v2 = redv[t + off]; int i2 = redi[t + off];
                if (v2 < redv[t] || (v2 == redv[t] && i2 < redi[t])) {
                    redv[t] = v2; redi[t] = i2;
                }
            }
            __syncthreads();
        }
        if (t == 0) { if (br) g_yidx2[j] = redi[0]; else g_yidx1[j] = redi[0]; }
        __syncthreads();
    }
}

// ---------------- phase C ----------------------------------------------------
// 128 threads (4 warps, JT=64), 2 CTAs/SM, CH=128, fp16 operands.
// smem (bytes): F 20480 | SL 11520 | MT 25856 | LI 512 | YJ 256 = 58624
#define SC_F  0
#define SC_SL 20480
#define SC_MT 32000
#define SC_LI 57856
#define SC_YJ 58368
#define SC_SIZE 58624

__global__ __launch_bounds__(128, 2)
void k_phaseC(const float* __restrict__ ld1, const float* __restrict__ ld2,
              const int* __restrict__ li1, const int* __restrict__ li2) {
    extern __shared__ char smem[];
    uint32_t* Fu  = (uint32_t*)(smem + SC_F);
    uint32_t* SLu = (uint32_t*)(smem + SC_SL);
    float* mt  = (float*)(smem + SC_MT);    // [64][101]
    int*   lib = (int*)(smem + SC_LI);      // [128]
    int*   yjs = (int*)(smem + SC_YJ);      // [64]
    const uint32_t Fb = su32(Fu), SLb = su32(SLu);

    const int tid = threadIdx.x;
    const int w = tid >> 5, lane = tid & 31;
    const int r0 = lane >> 2, c0l = lane & 3;
    const int jw = w * 16;
    const int j0 = blockIdx.x * 64;
    const int slab = blockIdx.y;
    const int br = blockIdx.z;
    const int ch0 = slab * CPS_C;
    const int ch1 = min(ch0 + CPS_C, NCH_TOT);
    const int nc = ch1 - ch0;

    const float* ld = br ? ld2 : ld1;
    const int*   li = br ? li2 : li1;
    const __half (*fh)[D_] = br ? g_f2h : g_f1h;
    const float* nxt = br ? g_nxt2 : g_nxt1;
    const int*   yix = br ? g_yidx2 : g_yidx1;
    float (*nump)[B_][DY_] = br ? g_num2_part : g_num1_part;
    float (*denp)[B_]      = br ? g_den2_part : g_den1_part;

    // A-fragments from g_xth (natural pairs)
    uint32_t aF[4][4];
    {
        const uint32_t* xr0 = (const uint32_t*)&g_xth[br][j0 + jw + r0][0];
        const uint32_t* xr1 = (const uint32_t*)&g_xth[br][j0 + jw + r0 + 8][0];
#pragma unroll
        for (int ks = 0; ks < 4; ks++) {
            aF[ks][0] = xr0[ks * 8 + c0l];
            aF[ks][1] = xr1[ks * 8 + c0l];
            aF[ks][2] = xr0[ks * 8 + c0l + 4];
            aF[ks][3] = xr1[ks * 8 + c0l + 4];
        }
    }
    const float nxt0 = nxt[j0 + jw + r0];
    const float nxt1 = nxt[j0 + jw + r0 + 8];
    if (tid < 64) yjs[tid] = yix[j0 + tid];
    __syncthreads();
    for (int idx = tid; idx < 64 * L_; idx += 128) {
        int j = idx / L_, l = idx - j * L_;
        mt[j * 101 + l] = __expf(-ETA_ * ld[l * L_ + yjs[j]]);
    }

    // chunk 0 loads
    {
        const int i0p = ch0 * 128;
        for (int idx = tid; idx < 128 * 8; idx += 128) {
            int r = idx >> 3, g = idx & 7;
            long gi = min(i0p + r, N_ - 1);
            CPA16(Fb + r * 160 + g * 16, (const char*)&fh[gi][0] + g * 16);
        }
        for (int idx = tid; idx < SL_ROWS * 16; idx += 128) {
            int r = idx >> 4, g = idx & 15;
            CPA16(SLb + r * 288 + g * 16, (const char*)&g_slh[br][r][i0p] + g * 16);
        }
        lib[tid] = li[min(i0p + tid, N_ - 1)];
        CP_COMMIT(); CP_WAIT0();
        __syncthreads();
    }

    float acc[5][4];
#pragma unroll
    for (int n = 0; n < 5; n++)
#pragma unroll
        for (int q = 0; q < 4; q++) acc[n][q] = 0.f;

    for (int c = 0; c < nc; c++) {
#pragma unroll
        for (int kc = 0; kc < 8; kc++) {
            float cf0[4] = {0.f, 0.f, 0.f, 0.f};
            float cf1[4] = {0.f, 0.f, 0.f, 0.f};
#pragma unroll
            for (int ks = 0; ks < 4; ks++) {
                uint2 q0 = *(const uint2*)&Fu[((2 * kc) * 8 + r0) * ST_STR + ks * 8 + 2 * c0l];
                uint32_t b0[2] = {q0.x, q0.y};
                mma16(cf0, aF[ks], b0);
                uint2 q1 = *(const uint2*)&Fu[((2 * kc + 1) * 8 + r0) * ST_STR + ks * 8 + 2 * c0l];
                uint32_t b1[2] = {q1.x, q1.y};
                mma16(cf1, aF[ks], b1);
            }
            const int ic0 = kc * 16 + 2 * c0l, ic1 = ic0 + 1;
            const int jc0 = ic0 + 8, jc1 = ic1 + 8;
            int l0 = lib[ic0], l1 = lib[ic1];
            int l2 = lib[jc0], l3 = lib[jc1];
            float m00 = mt[(jw + r0) * 101 + l0], m01 = mt[(jw + r0) * 101 + l1];
            float m10 = mt[(jw + r0 + 8) * 101 + l0], m11 = mt[(jw + r0 + 8) * 101 + l1];
            float m20 = mt[(jw + r0) * 101 + l2], m21 = mt[(jw + r0) * 101 + l3];
            float m30 = mt[(jw + r0 + 8) * 101 + l2], m31 = mt[(jw + r0 + 8) * 101 + l3];
            uint32_t a2[4];
            a2[0] = packh(__expf(2.f * cf0[0] - nxt0) * m00, __expf(2.f * cf0[1] - nxt0) * m01);
            a2[1] = packh(__expf(2.f * cf0[2] - nxt1) * m10, __expf(2.f * cf0[3] - nxt1) * m11);
            a2[2] = packh(__expf(2.f * cf1[0] - nxt0) * m20, __expf(2.f * cf1[1] - nxt0) * m21);
            a2[3] = packh(__expf(2.f * cf1[2] - nxt1) * m30, __expf(2.f * cf1[3] - nxt1) * m31);
#pragma unroll
            for (int nt2 = 0; nt2 < 5; nt2++) {
                uint2 q = *(const uint2*)&SLu[(nt2 * 8 + r0) * SL_STR + kc * 8 + 2 * c0l];
                uint32_t b[2] = {q.x, q.y};
                mma16(acc[nt2], a2, b);
            }
        }

        if (c + 1 < nc) {
            __syncthreads();
            const int i0n = (ch0 + c + 1) * 128;
            for (int idx = tid; idx < 128 * 8; idx += 128) {
                int r = idx >> 3, g = idx & 7;
                long gi = min(i0n + r, N_ - 1);
                CPA16(Fb + r * 160 + g * 16, (const char*)&fh[gi][0] + g * 16);
            }
            for (int idx = tid; idx < SL_ROWS * 16; idx += 128) {
                int r = idx >> 4, g = idx & 15;
                CPA16(SLb + r * 288 + g * 16, (const char*)&g_slh[br][r][i0n] + g * 16);
            }
            lib[tid] = li[min(i0n + tid, N_ - 1)];
            CP_COMMIT(); CP_WAIT0();
            __syncthreads();
        }
    }

    const int jr0 = j0 + jw + r0, jr1 = jr0 + 8;
#pragma unroll
    for (int nt = 0; nt < 5; nt++) {
        int n = nt * 8 + 2 * c0l;
        if (n < 32) {
            *(float2*)&nump[slab][jr0][n] = make_float2(acc[nt][0], acc[nt][1]);
            *(float2*)&nump[slab][jr1][n] = make_float2(acc[nt][2], acc[nt][3]);
        } else if (n == 32) {
            denp[slab][jr0] = acc[nt][0];
            denp[slab][jr1] = acc[nt][2];
        }
    }
}

// ---------------- K4: reduce partials ----------------------------------------
__global__ void k_out(float* __restrict__ out) {
    int gid = blockIdx.x * blockDim.x + threadIdx.x;
    if (gid >= B_ * DY_) return;
    int j = gid >> 5, dy = gid & 31;
    float n1 = 0.f, d1 = 0.f, n2 = 0.f, d2 = 0.f;
    for (int s = 0; s < NSLAB_C; s++) {
        n1 += g_num1_part[s][j][dy];
        d1 += g_den1_part[s][j];
        n2 += g_num2_part[s][j][dy];
        d2 += g_den2_part[s][j];
    }
    out[gid] = 0.5f * (n1 / d1 + n2 / d2);
}

// ---------------- launch -----------------------------------------------------
extern "C" void kernel_launch(void* const* d_in, const int* in_sizes, int n_in,
                              void* d_out, int out_size) {
    const float* x    = (const float*)d_in[0];
    const float* star = (const float*)d_in[1];
    const float* slb  = (const float*)d_in[2];
    const float* f1   = (const float*)d_in[3];
    const float* f2   = (const float*)d_in[4];
    const float* u1   = (const float*)d_in[5];
    const float* u2   = (const float*)d_in[6];
    const float* ld1  = (const float*)d_in[7];
    const float* ld2  = (const float*)d_in[8];
    const float* W1   = (const float*)d_in[9];
    const float* b1   = (const float*)d_in[10];
    const float* W2   = (const float*)d_in[11];
    const float* b2   = (const float*)d_in[12];
    const int*   li1  = (const int*)d_in[13];
    const int*   li2  = (const int*)d_in[14];
    float* out = (float*)d_out;

    cudaFuncSetAttribute(k_phaseA, cudaFuncAttributeMaxDynamicSharedMemorySize, SA_SIZE);
    cudaFuncSetAttribute(k_phaseC, cudaFuncAttributeMaxDynamicSharedMemorySize, SC_SIZE);

    k_prep<<<(B_ + 3 * N_ + 255) / 256, 256>>>(x, star, f1, f2);
    k_h1<<<((B_ + 3 * NP) * D_ + 255) / 256, 256>>>(x, star, f1, f2);
    k_h2<<<(FC_ROWS * NP + 255) / 256, 256>>>(f1, f2);
    k_h3<<<(2 * SL_ROWS * NP + 255) / 256, 256>>>(slb);
    k_phaseA<<<dim3(32, NSLAB_A), 128, SA_SIZE>>>();
    k_mid<<<B_, 128>>>(f1, f2, W1, b1, W2, b2, u1, u2);
    k_phaseC<<<dim3(32, NSLAB_C, 2), 128, SC_SIZE>>>(ld1, ld2, li1, li2);
    k_out<<<(B_ * DY_ + 255) / 256, 256>>>(out);
}

// round 16
// speedup vs baseline: 1.6059x; 1.0359x over previous
#include <cuda_runtime.h>
#include <cuda_fp16.h>
#include <cstdint>
#include <cfloat>

// Problem constants (fixed shapes for MergeNN_38903813767173)
#define B_ 2048
#define N_ 20000
#define D_ 64
#define DY_ 32
#define L_ 100
#define ETA_ 0.01f

#define NP 20224            // 158*128 padded i-extent
#define NCH_TOT 158
#define NSLAB_A 9
#define CPS_A 18            // grid 32*9 = 288 <= 296 (2 CTA/SM, one wave)
#define NSLAB_C 4
#define CPS_C 40            // grid 32*4*2 = 256 <= 296

#define ST_STR 40           // fp16 star/f smem row stride in u32 (160B; 40%32=8 conflict-free)
#define FC_STR 72           // fp16 fcomb smem row stride in u32 (288B; 72%32=8)
#define SL_STR 72
#define FC_ROWS 136         // 64+64+1+7 pad
#define SL_ROWS 40          // 32+1+7 pad

// ---------------- helpers ----------------------------------------------------
__device__ __forceinline__ uint32_t su32(const void* p) {
    return (uint32_t)__cvta_generic_to_shared(p);
}
#define CPA16(dst, src) \
    asm volatile("cp.async.ca.shared.global [%0], [%1], 16;" :: "r"(dst), "l"(src))
#define CP_COMMIT() asm volatile("cp.async.commit_group;")
#define CP_WAIT0()  asm volatile("cp.async.wait_group 0;" ::: "memory")

__device__ __forceinline__ uint32_t packh(float lo, float hi) {
    __half2 h = __floats2half2_rn(lo, hi);
    return *(uint32_t*)&h;
}
// fp16 m16n8k16: K=16 per instruction, fp32 accumulate
__device__ __forceinline__ void mma16(float c[4], const uint32_t a[4], const uint32_t b[2]) {
    asm volatile("mma.sync.aligned.m16n8k16.row.col.f32.f16.f16.f32 "
                 "{%0,%1,%2,%3}, {%4,%5,%6,%7}, {%8,%9}, {%0,%1,%2,%3};"
                 : "+f"(c[0]), "+f"(c[1]), "+f"(c[2]), "+f"(c[3])
                 : "r"(a[0]), "r"(a[1]), "r"(a[2]), "r"(a[3]), "r"(b[0]), "r"(b[1]));
}

// storage slot s (within 8-slot u32 group) holds physical pair (s even ? s/2 : s/2+4)
__device__ __forceinline__ int physpos(int stor) {
    int g = stor & ~15, s = (stor >> 1) & 7, e = stor & 1;
    int p = (s & 1) ? (s >> 1) + 4 : (s >> 1);
    return g + 2 * p + e;
}
// inverse: storage index for physical element i
__device__ __forceinline__ int istor(int i) {
    int g = i & ~15, p = (i >> 1) & 7, e = i & 1;
    int s = (p < 4) ? 2 * p : 2 * (p - 4) + 1;
    return g + 2 * s + e;
}

// ---------------- scratch ----------------------------------------------------
__device__ float g_nx[B_];
__device__ float g_ns[N_];
__device__ float g_nf1[N_];
__device__ float g_nf2[N_];
__device__ int   g_match[B_];

__device__ __half g_xh[B_][D_];        // x, fp16, natural d
__device__ __half g_sth[NP][D_];       // star, fp16, d-pairs slot-permuted
__device__ __half g_f1h[NP][D_];       // f1, fp16, d-pairs slot-permuted
__device__ __half g_f2h[NP][D_];
__device__ __half g_fch[FC_ROWS][NP];  // e^{-ns}[f1|f2|1|0], fp16, i-pairs slot-permuted
__device__ __half g_slh[2][SL_ROWS][NP]; // e^{-nf}[slb|1|0], fp16, i-pairs slot-permuted
__device__ __half g_xth[2][B_][D_];    // xt, fp16, natural d (written by k_mid)

__device__ float g_esum_part[NSLAB_A][B_];
__device__ float g_acc1_part[NSLAB_A][B_][D_];
__device__ float g_acc2_part[NSLAB_A][B_][D_];

__device__ float g_xt1[B_][D_];
__device__ float g_xt2[B_][D_];
__device__ float g_nxt1[B_];
__device__ float g_nxt2[B_];
__device__ int   g_yidx1[B_];
__device__ int   g_yidx2[B_];

__device__ float g_num1_part[NSLAB_C][B_][DY_];
__device__ float g_num2_part[NSLAB_C][B_][DY_];
__device__ float g_den1_part[NSLAB_C][B_];
__device__ float g_den2_part[NSLAB_C][B_];

// ---------------- K0: norms + match init -------------------------------------
__global__ void k_prep(const float* __restrict__ x, const float* __restrict__ star,
                       const float* __restrict__ f1, const float* __restrict__ f2) {
    int gid = blockIdx.x * blockDim.x + threadIdx.x;
    const float* src;
    float* dst;
    if (gid < B_) {
        g_match[gid] = 0x7fffffff;
        src = x + gid * D_;        dst = &g_nx[gid];
    } else if (gid < B_ + N_) {
        int r = gid - B_;          src = star + r * D_; dst = &g_ns[r];
    } else if (gid < B_ + 2 * N_) {
        int r = gid - B_ - N_;     src = f1 + r * D_;   dst = &g_nf1[r];
    } else if (gid < B_ + 3 * N_) {
        int r = gid - B_ - 2 * N_; src = f2 + r * D_;   dst = &g_nf2[r];
    } else return;
    float s = 0.f;
    const float4* p = reinterpret_cast<const float4*>(src);
#pragma unroll
    for (int i = 0; i < 16; i++) {
        float4 v = p[i];
        s += v.x * v.x + v.y * v.y + v.z * v.z + v.w * v.w;
    }
    *dst = s;
}

// ---------------- K0b: fp16 x (natural) + star/f1/f2 (permuted) --------------
// reads are coalesced (consecutive d within a row); permutation only swaps
// 32-bit slots within 32B subgroups, so effective access stays sector-coalesced.
__global__ void k_h1(const float* __restrict__ x, const float* __restrict__ star,
                     const float* __restrict__ f1, const float* __restrict__ f2) {
    int gid = blockIdx.x * blockDim.x + threadIdx.x;
    if (gid < B_ * D_) {
        ((__half*)g_xh)[gid] = __float2half(x[gid]);
        return;
    }
    gid -= B_ * D_;
    if (gid >= 3 * NP * D_) return;
    int which = gid / (NP * D_);
    int rem = gid - which * (NP * D_);
    int i = rem >> 6, d = rem & 63;     // d = storage index
    int dp = physpos(d);
    float v = 0.f;
    if (i < N_) {
        const float* src = (which == 0) ? star : ((which == 1) ? f1 : f2);
        v = src[(long)i * D_ + dp];
    }
    __half hv = __float2half(v);
    if (which == 0) g_sth[i][d] = hv;
    else if (which == 1) g_f1h[i][d] = hv;
    else g_f2h[i][d] = hv;
}

// ---------------- K0c: fp16 fcomb (smem tile transpose, i-permuted write) ----
__global__ void k_h2(const float* __restrict__ f1, const float* __restrict__ f2) {
    __shared__ float ts[32][33];
    int tx = threadIdx.x, ty = threadIdx.y;
    int i0 = blockIdx.x * 32;
    int by = blockIdx.y;
    int i = i0 + tx;                     // physical i (coalesced reads)
    int ic = i0 + istor(tx);             // storage column (write)
    float sc = (i < N_) ? __expf(-g_ns[i]) : 0.f;
    if (by == 4) {
        for (int r = 128 + ty; r < FC_ROWS; r += 8)
            g_fch[r][ic] = __float2half((r == 128) ? sc : 0.f);
        return;
    }
    const float* src = (by < 2) ? f1 : f2;
    int d0 = (by & 1) * 32;
    int rowbase = by * 32;
#pragma unroll
    for (int q = 0; q < 4; q++) {
        int r = ty + q * 8;
        ts[r][tx] = src[(long)min(i0 + r, N_ - 1) * 64 + d0 + tx];
    }
    __syncthreads();
#pragma unroll
    for (int q = 0; q < 4; q++) {
        int d = ty + q * 8;
        g_fch[rowbase + d][ic] = __float2half((i < N_) ? ts[tx][d] * sc : 0.f);
    }
}

// ---------------- K0d: fp16 slbcomb (smem tile transpose, i-permuted write) --
__global__ void k_h3(const float* __restrict__ slb) {
    __shared__ float ts[32][33];
    int tx = threadIdx.x, ty = threadIdx.y;
    int i0 = blockIdx.x * 32;
    int br = blockIdx.z;
    int i = i0 + tx;
    int ic = i0 + istor(tx);
    float sc = (i < N_) ? __expf(-(br ? g_nf2[i] : g_nf1[i])) : 0.f;
#pragma unroll
    for (int q = 0; q < 4; q++) {
        int r = ty + q * 8;
        ts[r][tx] = slb[(long)min(i0 + r, N_ - 1) * 32 + tx];
    }
    __syncthreads();
#pragma unroll
    for (int q = 0; q < 4; q++) {
        int d = ty + q * 8;
        g_slh[br][d][ic] = __float2half((i < N_) ? ts[tx][d] * sc : 0.f);
    }
    if (ty == 0) g_slh[br][32][ic] = __float2half(sc);
    for (int r = 33 + ty; r < SL_ROWS; r += 8) g_slh[br][r][ic] = __float2half(0.f);
}

// ---------------- phase A ----------------------------------------------------
// 128 threads (4 warps, JT=64), 2 CTAs/SM, CH=128, fp16 operands.
// smem (bytes): ST 20480 | FC 39168 | NS 512 = 60160
#define SA_ST 0
#define SA_FC 20480
#define SA_NS 59648
#define SA_SIZE 60160

__global__ __launch_bounds__(128, 2)
void k_phaseA() {
    extern __shared__ char smem[];
    uint32_t* STu = (uint32_t*)(smem + SA_ST);
    uint32_t* FCu = (uint32_t*)(smem + SA_FC);
    float* nsb = (float*)(smem + SA_NS);   // [128]
    const uint32_t STb = su32(STu), FCb = su32(FCu);

    const int tid = threadIdx.x;
    const int w = tid >> 5, lane = tid & 31;
    const int r0 = lane >> 2, c0l = lane & 3;
    const int jw = w * 16;
    const int j0 = blockIdx.x * 64;
    const int slab = blockIdx.y;
    const int ch0 = slab * CPS_A;
    const int ch1 = min(ch0 + CPS_A, NCH_TOT);
    const int nc = ch1 - ch0;

    // A-fragments from g_xh (natural pairs: pair p at u32 slot p)
    uint32_t aF[4][4];
    {
        const uint32_t* xr0 = (const uint32_t*)&g_xh[j0 + jw + r0][0];
        const uint32_t* xr1 = (const uint32_t*)&g_xh[j0 + jw + r0 + 8][0];
#pragma unroll
        for (int ks = 0; ks < 4; ks++) {
            aF[ks][0] = xr0[ks * 8 + c0l];
            aF[ks][1] = xr1[ks * 8 + c0l];
            aF[ks][2] = xr0[ks * 8 + c0l + 4];
            aF[ks][3] = xr1[ks * 8 + c0l + 4];
        }
    }
    const float nx0 = g_nx[j0 + jw + r0];
    const float nx1 = g_nx[j0 + jw + r0 + 8];

    // chunk 0 loads
    {
        const int i0p = ch0 * 128;
        for (int idx = tid; idx < 128 * 8; idx += 128) {
            int r = idx >> 3, g = idx & 7;
            long gi = min(i0p + r, N_ - 1);
            CPA16(STb + r * 160 + g * 16, (const char*)&g_sth[gi][0] + g * 16);
        }
        for (int idx = tid; idx < FC_ROWS * 16; idx += 128) {
            int r = idx >> 4, g = idx & 15;
            CPA16(FCb + r * 288 + g * 16, (const char*)&g_fch[r][i0p] + g * 16);
        }
        { int gi = i0p + tid; nsb[tid] = (gi < N_) ? g_ns[gi] : 1e30f; }
        CP_COMMIT(); CP_WAIT0();
        __syncthreads();
    }

    float acc[17][4];
#pragma unroll
    for (int n = 0; n < 17; n++)
#pragma unroll
        for (int q = 0; q < 4; q++) acc[n][q] = 0.f;

    for (int c = 0; c < nc; c++) {
        const int i0 = (ch0 + c) * 128;

        // fused per kc (16 i's): MMA1 (nt=2kc,2kc+1) -> exp -> MMA2(kc)
#pragma unroll
        for (int kc = 0; kc < 8; kc++) {
            float cf0[4] = {0.f, 0.f, 0.f, 0.f};
            float cf1[4] = {0.f, 0.f, 0.f, 0.f};
#pragma unroll
            for (int ks = 0; ks < 4; ks++) {
                uint2 q0 = *(const uint2*)&STu[((2 * kc) * 8 + r0) * ST_STR + ks * 8 + 2 * c0l];
                uint32_t b0[2] = {q0.x, q0.y};
                mma16(cf0, aF[ks], b0);
                uint2 q1 = *(const uint2*)&STu[((2 * kc + 1) * 8 + r0) * ST_STR + ks * 8 + 2 * c0l];
                uint32_t b1[2] = {q1.x, q1.y};
                mma16(cf1, aF[ks], b1);
            }
            const int ic0 = kc * 16 + 2 * c0l, ic1 = ic0 + 1;
            const int jc0 = ic0 + 8, jc1 = ic1 + 8;
            float ns0 = nsb[ic0], ns1 = nsb[ic1];
            float ns2 = nsb[jc0], ns3 = nsb[jc1];
            float t00 = 2.f * cf0[0] - nx0, t01 = 2.f * cf0[1] - nx0;
            float t10 = 2.f * cf0[2] - nx1, t11 = 2.f * cf0[3] - nx1;
            float t20 = 2.f * cf1[0] - nx0, t21 = 2.f * cf1[1] - nx0;
            float t30 = 2.f * cf1[2] - nx1, t31 = 2.f * cf1[3] - nx1;
            if (t00 >= ns0) atomicMin(&g_match[j0 + jw + r0], i0 + ic0);
            if (t01 >= ns1) atomicMin(&g_match[j0 + jw + r0], i0 + ic1);
            if (t10 >= ns0) atomicMin(&g_match[j0 + jw + r0 + 8], i0 + ic0);
            if (t11 >= ns1) atomicMin(&g_match[j0 + jw + r0 + 8], i0 + ic1);
            if (t20 >= ns2) atomicMin(&g_match[j0 + jw + r0], i0 + jc0);
            if (t21 >= ns3) atomicMin(&g_match[j0 + jw + r0], i0 + jc1);
            if (t30 >= ns2) atomicMin(&g_match[j0 + jw + r0 + 8], i0 + jc0);
            if (t31 >= ns3) atomicMin(&g_match[j0 + jw + r0 + 8], i0 + jc1);
            uint32_t a2[4];
            a2[0] = packh(__expf(t00), __expf(t01));
            a2[1] = packh(__expf(t10), __expf(t11));
            a2[2] = packh(__expf(t20), __expf(t21));
            a2[3] = packh(__expf(t30), __expf(t31));
#pragma unroll
            for (int nt2 = 0; nt2 < 17; nt2++) {
                uint2 q = *(const uint2*)&FCu[(nt2 * 8 + r0) * FC_STR + kc * 8 + 2 * c0l];
                uint32_t b[2] = {q.x, q.y};
                mma16(acc[nt2], a2, b);
            }
        }

        // reload (cross-CTA overlap hides this)
        if (c + 1 < nc) {
            __syncthreads();
            const int i0n = i0 + 128;
            for (int idx = tid; idx < 128 * 8; idx += 128) {
                int r = idx >> 3, g = idx & 7;
                long gi = min(i0n + r, N_ - 1);
                CPA16(STb + r * 160 + g * 16, (const char*)&g_sth[gi][0] + g * 16);
            }
            for (int idx = tid; idx < FC_ROWS * 16; idx += 128) {
                int r = idx >> 4, g = idx & 15;
                CPA16(FCb + r * 288 + g * 16, (const char*)&g_fch[r][i0n] + g * 16);
            }
            { int gi = i0n + tid; nsb[tid] = (gi < N_) ? g_ns[gi] : 1e30f; }
            CP_COMMIT(); CP_WAIT0();
            __syncthreads();
        }
    }

    // writeback
    const int jr0 = j0 + jw + r0, jr1 = jr0 + 8;
#pragma unroll
    for (int nt = 0; nt < 17; nt++) {
        int n = nt * 8 + 2 * c0l;
        if (n < 64) {
            *(float2*)&g_acc1_part[slab][jr0][n] = make_float2(acc[nt][0], acc[nt][1]);
            *(float2*)&g_acc1_part[slab][jr1][n] = make_float2(acc[nt][2], acc[nt][3]);
        } else if (n < 128) {
            *(float2*)&g_acc2_part[slab][jr0][n - 64] = make_float2(acc[nt][0], acc[nt][1]);
            *(float2*)&g_acc2_part[slab][jr1][n - 64] = make_float2(acc[nt][2], acc[nt][3]);
        } else if (n == 128) {
            g_esum_part[slab][jr0] = acc[nt][0];
            g_esum_part[slab][jr1] = acc[nt][2];
        }
    }
}

// ---------------- K2: middle — xt, y = xt@W+b, argmin label ------------------
__global__ __launch_bounds__(128)
void k_mid(const float* __restrict__ f1, const float* __restrict__ f2,
           const float* __restrict__ W1, const float* __restrict__ b1,
           const float* __restrict__ W2, const float* __restrict__ b2,
           const float* __restrict__ u1, const float* __restrict__ u2) {
    int j = blockIdx.x;
    int t = threadIdx.x;

    __shared__ float xts[D_];
    __shared__ float ys[DY_];
    __shared__ float esum_s;
    __shared__ float ny_s;
    __shared__ float redv[128];
    __shared__ int   redi[128];

    int  mi = g_match[j];
    bool hm = (mi != 0x7fffffff);
    if (t == 0) {
        float s = 0.f;
        for (int k = 0; k < NSLAB_A; k++) s += g_esum_part[k][j];
        esum_s = s;
    }
    __syncthreads();

    for (int br = 0; br < 2; br++) {
        const float* f  = br ? f2 : f1;
        const float* W  = br ? W2 : W1;
        const float* bb = br ? b2 : b1;
        const float* u  = br ? u2 : u1;

        if (t < D_) {
            float a = 0.f;
            if (br) { for (int k = 0; k < NSLAB_A; k++) a += g_acc2_part[k][j][t]; }
            else    { for (int k = 0; k < NSLAB_A; k++) a += g_acc1_part[k][j][t]; }
            float v = hm ? f[mi * D_ + t] : a / esum_s;
            xts[t] = v;
            if (br) g_xt2[j][t] = v; else g_xt1[j][t] = v;
            g_xth[br][j][t] = __float2half(v);
        }
        __syncthreads();
        if (t == 0) {
            float s = 0.f;
            for (int d = 0; d < D_; d++) s += xts[d] * xts[d];
            if (br) g_nxt2[j] = s; else g_nxt1[j] = s;
        }
        if (t < DY_) {
            float a = bb[t];
            for (int d = 0; d < D_; d++) a += xts[d] * W[d * DY_ + t];
            ys[t] = a;
        }
        __syncthreads();
        if (t == 0) {
            float s = 0.f;
            for (int dy = 0; dy < DY_; dy++) s += ys[dy] * ys[dy];
            ny_s = s;
        }
        __syncthreads();

        float v = FLT_MAX;
        int   vi = 0x7fffffff;
        if (t < L_) {
            float nu = 0.f, dot = 0.f;
            for (int dy = 0; dy < DY_; dy++) {
                float uu = u[t * DY_ + dy];
                nu += uu * uu;
                dot += uu * ys[dy];
            }
            v = fmaxf(ny_s + nu - 2.f * dot, 0.f);
            vi = t;
        }
        redv[t] = v; redi[t] = vi;
        __syncthreads();
        for (int off = 64; off > 0; off >>= 1) {
            if (t < off) {
                float v2 = redv[t + off]; int i2 = redi[t + off];
                if (v2 < redv[t] || (v2 == redv[t] && i2 < redi[t])) {
                    redv[t] = v2; redi[t] = i2;
                }
            }
            __syncthreads();
        }
        if (t == 0) { if (br) g_yidx2[j] = redi[0]; else g_yidx1[j] = redi[0]; }
        __syncthreads();
    }
}

// ---------------- phase C ----------------------------------------------------
// 128 threads (4 warps, JT=64), 2 CTAs/SM, CH=128, fp16 operands.
// smem (bytes): F 20480 | SL 11520 | MT 25856 | LI 512 | YJ 256 = 58624
#define SC_F  0
#define SC_SL 20480
#define SC_MT 32000
#define SC_LI 57856
#define SC_YJ 58368
#define SC_SIZE 58624

__global__ __launch_bounds__(128, 2)
void k_phaseC(const float* __restrict__ ld1, const float* __restrict__ ld2,
              const int* __restrict__ li1, const int* __restrict__ li2) {
    extern __shared__ char smem[];
    uint32_t* Fu  = (uint32_t*)(smem + SC_F);
    uint32_t* SLu = (uint32_t*)(smem + SC_SL);
    float* mt  = (float*)(smem + SC_MT);    // [64][101]
    int*   lib = (int*)(smem + SC_LI);      // [128]
    int*   yjs = (int*)(smem + SC_YJ);      // [64]
    const uint32_t Fb = su32(Fu), SLb = su32(SLu);

    const int tid = threadIdx.x;
    const int w = tid >> 5, lane = tid & 31;
    const int r0 = lane >> 2, c0l = lane & 3;
    const int jw = w * 16;
    const int j0 = blockIdx.x * 64;
    const int slab = blockIdx.y;
    const int br = blockIdx.z;
    const int ch0 = slab * CPS_C;
    const int ch1 = min(ch0 + CPS_C, NCH_TOT);
    const int nc = ch1 - ch0;

    const float* ld = br ? ld2 : ld1;
    const int*   li = br ? li2 : li1;
    const __half (*fh)[D_] = br ? g_f2h : g_f1h;
    const float* nxt = br ? g_nxt2 : g_nxt1;
    const int*   yix = br ? g_yidx2 : g_yidx1;
    float (*nump)[B_][DY_] = br ? g_num2_part : g_num1_part;
    float (*denp)[B_]      = br ? g_den2_part : g_den1_part;

    // A-fragments from g_xth (natural pairs)
    uint32_t aF[4][4];
    {
        const uint32_t* xr0 = (const uint32_t*)&g_xth[br][j0 + jw + r0][0];
        const uint32_t* xr1 = (const uint32_t*)&g_xth[br][j0 + jw + r0 + 8][0];
#pragma unroll
        for (int ks = 0; ks < 4; ks++) {
            aF[ks][0] = xr0[ks * 8 + c0l];
            aF[ks][1] = xr1[ks * 8 + c0l];
            aF[ks][2] = xr0[ks * 8 + c0l + 4];
            aF[ks][3] = xr1[ks * 8 + c0l + 4];
        }
    }
    const float nxt0 = nxt[j0 + jw + r0];
    const float nxt1 = nxt[j0 + jw + r0 + 8];
    if (tid < 64) yjs[tid] = yix[j0 + tid];
    __syncthreads();
    for (int idx = tid; idx < 64 * L_; idx += 128) {
        int j = idx / L_, l = idx - j * L_;
        mt[j * 101 + l] = __expf(-ETA_ * ld[l * L_ + yjs[j]]);
    }

    // chunk 0 loads
    {
        const int i0p = ch0 * 128;
        for (int idx = tid; idx < 128 * 8; idx += 128) {
            int r = idx >> 3, g = idx & 7;
            long gi = min(i0p + r, N_ - 1);
            CPA16(Fb + r * 160 + g * 16, (const char*)&fh[gi][0] + g * 16);
        }
        for (int idx = tid; idx < SL_ROWS * 16; idx += 128) {
            int r = idx >> 4, g = idx & 15;
            CPA16(SLb + r * 288 + g * 16, (const char*)&g_slh[br][r][i0p] + g * 16);
        }
        lib[tid] = li[min(i0p + tid, N_ - 1)];
        CP_COMMIT(); CP_WAIT0();
        __syncthreads();
    }

    float acc[5][4];
#pragma unroll
    for (int n = 0; n < 5; n++)
#pragma unroll
        for (int q = 0; q < 4; q++) acc[n][q] = 0.f;

    for (int c = 0; c < nc; c++) {
#pragma unroll
        for (int kc = 0; kc < 8; kc++) {
            float cf0[4] = {0.f, 0.f, 0.f, 0.f};
            float cf1[4] = {0.f, 0.f, 0.f, 0.f};
#pragma unroll
            for (int ks = 0; ks < 4; ks++) {
                uint2 q0 = *(const uint2*)&Fu[((2 * kc) * 8 + r0) * ST_STR + ks * 8 + 2 * c0l];
                uint32_t b0[2] = {q0.x, q0.y};
                mma16(cf0, aF[ks], b0);
                uint2 q1 = *(const uint2*)&Fu[((2 * kc + 1) * 8 + r0) * ST_STR + ks * 8 + 2 * c0l];
                uint32_t b1[2] = {q1.x, q1.y};
                mma16(cf1, aF[ks], b1);
            }
            const int ic0 = kc * 16 + 2 * c0l, ic1 = ic0 + 1;
            const int jc0 = ic0 + 8, jc1 = ic1 + 8;
            int l0 = lib[ic0], l1 = lib[ic1];
            int l2 = lib[jc0], l3 = lib[jc1];
            float m00 = mt[(jw + r0) * 101 + l0], m01 = mt[(jw + r0) * 101 + l1];
            float m10 = mt[(jw + r0 + 8) * 101 + l0], m11 = mt[(jw + r0 + 8) * 101 + l1];
            float m20 = mt[(jw + r0) * 101 + l2], m21 = mt[(jw + r0) * 101 + l3];
            float m30 = mt[(jw + r0 + 8) * 101 + l2], m31 = mt[(jw + r0 + 8) * 101 + l3];
            uint32_t a2[4];
            a2[0] = packh(__expf(2.f * cf0[0] - nxt0) * m00, __expf(2.f * cf0[1] - nxt0) * m01);
            a2[1] = packh(__expf(2.f * cf0[2] - nxt1) * m10, __expf(2.f * cf0[3] - nxt1) * m11);
            a2[2] = packh(__expf(2.f * cf1[0] - nxt0) * m20, __expf(2.f * cf1[1] - nxt0) * m21);
            a2[3] = packh(__expf(2.f * cf1[2] - nxt1) * m30, __expf(2.f * cf1[3] - nxt1) * m31);
#pragma unroll
            for (int nt2 = 0; nt2 < 5; nt2++) {
                uint2 q = *(const uint2*)&SLu[(nt2 * 8 + r0) * SL_STR + kc * 8 + 2 * c0l];
                uint32_t b[2] = {q.x, q.y};
                mma16(acc[nt2], a2, b);
            }
        }

        if (c + 1 < nc) {
            __syncthreads();
            const int i0n = (ch0 + c + 1) * 128;
            for (int idx = tid; idx < 128 * 8; idx += 128) {
                int r = idx >> 3, g = idx & 7;
                long gi = min(i0n + r, N_ - 1);
                CPA16(Fb + r * 160 + g * 16, (const char*)&fh[gi][0] + g * 16);
            }
            for (int idx = tid; idx < SL_ROWS * 16; idx += 128) {
                int r = idx >> 4, g = idx & 15;
                CPA16(SLb + r * 288 + g * 16, (const char*)&g_slh[br][r][i0n] + g * 16);
            }
            lib[tid] = li[min(i0n + tid, N_ - 1)];
            CP_COMMIT(); CP_WAIT0();
            __syncthreads();
        }
    }

    const int jr0 = j0 + jw + r0, jr1 = jr0 + 8;
#pragma unroll
    for (int nt = 0; nt < 5; nt++) {
        int n = nt * 8 + 2 * c0l;
        if (n < 32) {
            *(float2*)&nump[slab][jr0][n] = make_float2(acc[nt][0], acc[nt][1]);
            *(float2*)&nump[slab][jr1][n] = make_float2(acc[nt][2], acc[nt][3]);
        } else if (n == 32) {
            denp[slab][jr0] = acc[nt][0];
            denp[slab][jr1] = acc[nt][2];
        }
    }
}

// ---------------- K4: reduce partials ----------------------------------------
__global__ void k_out(float* __restrict__ out) {
    int gid = blockIdx.x * blockDim.x + threadIdx.x;
    if (gid >= B_ * DY_) return;
    int j = gid >> 5, dy = gid & 31;
    float n1 = 0.f, d1 = 0.f, n2 = 0.f, d2 = 0.f;
    for (int s = 0; s < NSLAB_C; s++) {
        n1 += g_num1_part[s][j][dy];
        d1 += g_den1_part[s][j];
        n2 += g_num2_part[s][j][dy];
        d2 += g_den2_part[s][j];
    }
    out[gid] = 0.5f * (n1 / d1 + n2 / d2);
}

// ---------------- launch -----------------------------------------------------
extern "C" void kernel_launch(void* const* d_in, const int* in_sizes, int n_in,
                              void* d_out, int out_size) {
    const float* x    = (const float*)d_in[0];
    const float* star = (const float*)d_in[1];
    const float* slb  = (const float*)d_in[2];
    const float* f1   = (const float*)d_in[3];
    const float* f2   = (const float*)d_in[4];
    const float* u1   = (const float*)d_in[5];
    const float* u2   = (const float*)d_in[6];
    const float* ld1  = (const float*)d_in[7];
    const float* ld2  = (const float*)d_in[8];
    const float* W1   = (const float*)d_in[9];
    const float* b1   = (const float*)d_in[10];
    const float* W2   = (const float*)d_in[11];
    const float* b2   = (const float*)d_in[12];
    const int*   li1  = (const int*)d_in[13];
    const int*   li2  = (const int*)d_in[14];
    float* out = (float*)d_out;

    cudaFuncSetAttribute(k_phaseA, cudaFuncAttributeMaxDynamicSharedMemorySize, SA_SIZE);
    cudaFuncSetAttribute(k_phaseC, cudaFuncAttributeMaxDynamicSharedMemorySize, SC_SIZE);

    k_prep<<<(B_ + 3 * N_ + 255) / 256, 256>>>(x, star, f1, f2);
    k_h1<<<((B_ + 3 * NP) * D_ + 255) / 256, 256>>>(x, star, f1, f2);
    k_h2<<<dim3(NP / 32, 5), dim3(32, 8)>>>(f1, f2);
    k_h3<<<dim3(NP / 32, 1, 2), dim3(32, 8)>>>(slb);
    k_phaseA<<<dim3(32, NSLAB_A), 128, SA_SIZE>>>();
    k_mid<<<B_, 128>>>(f1, f2, W1, b1, W2, b2, u1, u2);
    k_phaseC<<<dim3(32, NSLAB_C, 2), 128, SC_SIZE>>>(ld1, ld2, li1, li2);
    k_out<<<(B_ * DY_ + 255) / 256, 256>>>(out);
}

// round 17
// speedup vs baseline: 1.6751x; 1.0431x over previous
#include <cuda_runtime.h>
#include <cuda_fp16.h>
#include <cstdint>
#include <cfloat>

// Problem constants (fixed shapes for MergeNN_38903813767173)
#define B_ 2048
#define N_ 20000
#define D_ 64
#define DY_ 32
#define L_ 100
#define ETA_ 0.01f
#define L2E_ 1.4426950408889634f
#define TWO_L2E_ 2.8853900817779268f

#define NP 20224            // 158*128 padded i-extent
#define NCH_TOT 158
#define NSLAB_A 9
#define CPS_A 18            // grid 32*9 = 288 <= 296 (2 CTA/SM, one wave)
#define NSLAB_C 4
#define CPS_C 40            // grid 32*4*2 = 256 <= 296

#define ST_STR 40           // fp16 star/f smem row stride in u32 (160B; 40%32=8 conflict-free)
#define FC_STR 72           // fp16 fcomb smem row stride in u32 (288B; 72%32=8)
#define SL_STR 72
#define FC_ROWS 136         // 64+64+1+7 pad
#define SL_ROWS 40          // 32+1+7 pad

// ---------------- helpers ----------------------------------------------------
__device__ __forceinline__ uint32_t su32(const void* p) {
    return (uint32_t)__cvta_generic_to_shared(p);
}
#define CPA16(dst, src) \
    asm volatile("cp.async.ca.shared.global [%0], [%1], 16;" :: "r"(dst), "l"(src))
#define CP_COMMIT() asm volatile("cp.async.commit_group;")
#define CP_WAIT0()  asm volatile("cp.async.wait_group 0;" ::: "memory")

__device__ __forceinline__ uint32_t packh(float lo, float hi) {
    __half2 h = __floats2half2_rn(lo, hi);
    return *(uint32_t*)&h;
}
// exp2 on packed half2 (one MUFU pass; f16-rounded — same quantization as packh(expf))
__device__ __forceinline__ uint32_t ex2h2(float lo, float hi) {
    uint32_t p = packh(lo, hi), r;
    asm("ex2.approx.f16x2 %0, %1;" : "=r"(r) : "r"(p));
    return r;
}
// fp16 m16n8k16: K=16 per instruction, fp32 accumulate
__device__ __forceinline__ void mma16(float c[4], const uint32_t a[4], const uint32_t b[2]) {
    asm volatile("mma.sync.aligned.m16n8k16.row.col.f32.f16.f16.f32 "
                 "{%0,%1,%2,%3}, {%4,%5,%6,%7}, {%8,%9}, {%0,%1,%2,%3};"
                 : "+f"(c[0]), "+f"(c[1]), "+f"(c[2]), "+f"(c[3])
                 : "r"(a[0]), "r"(a[1]), "r"(a[2]), "r"(a[3]), "r"(b[0]), "r"(b[1]));
}

// storage slot s (within 8-slot u32 group) holds physical pair (s even ? s/2 : s/2+4)
__device__ __forceinline__ int physpos(int stor) {
    int g = stor & ~15, s = (stor >> 1) & 7, e = stor & 1;
    int p = (s & 1) ? (s >> 1) + 4 : (s >> 1);
    return g + 2 * p + e;
}
// inverse: storage index for physical element i
__device__ __forceinline__ int istor(int i) {
    int g = i & ~15, p = (i >> 1) & 7, e = i & 1;
    int s = (p < 4) ? 2 * p : 2 * (p - 4) + 1;
    return g + 2 * s + e;
}

// ---------------- scratch ----------------------------------------------------
__device__ float g_nx[B_];
__device__ float g_ns[N_];
__device__ float g_nf1[N_];
__device__ float g_nf2[N_];
__device__ int   g_match[B_];

__device__ __half g_xh[B_][D_];        // x, fp16, natural d
__device__ __half g_sth[NP][D_];       // star, fp16, d-pairs slot-permuted
__device__ __half g_f1h[NP][D_];       // f1, fp16, d-pairs slot-permuted
__device__ __half g_f2h[NP][D_];
__device__ __half g_fch[FC_ROWS][NP];  // e^{-ns}[f1|f2|1|0], fp16, i-pairs slot-permuted
__device__ __half g_slh[2][SL_ROWS][NP]; // e^{-nf}[slb|1|0], fp16, i-pairs slot-permuted
__device__ __half g_xth[2][B_][D_];    // xt, fp16, natural d (written by k_mid)

__device__ float g_esum_part[NSLAB_A][B_];
__device__ float g_acc1_part[NSLAB_A][B_][D_];
__device__ float g_acc2_part[NSLAB_A][B_][D_];

__device__ float g_xt1[B_][D_];
__device__ float g_xt2[B_][D_];
__device__ float g_nxt1[B_];
__device__ float g_nxt2[B_];
__device__ int   g_yidx1[B_];
__device__ int   g_yidx2[B_];

__device__ float g_num1_part[NSLAB_C][B_][DY_];
__device__ float g_num2_part[NSLAB_C][B_][DY_];
__device__ float g_den1_part[NSLAB_C][B_];
__device__ float g_den2_part[NSLAB_C][B_];

// ---------------- K0: norms + match init -------------------------------------
__global__ void k_prep(const float* __restrict__ x, const float* __restrict__ star,
                       const float* __restrict__ f1, const float* __restrict__ f2) {
    int gid = blockIdx.x * blockDim.x + threadIdx.x;
    const float* src;
    float* dst;
    if (gid < B_) {
        g_match[gid] = 0x7fffffff;
        src = x + gid * D_;        dst = &g_nx[gid];
    } else if (gid < B_ + N_) {
        int r = gid - B_;          src = star + r * D_; dst = &g_ns[r];
    } else if (gid < B_ + 2 * N_) {
        int r = gid - B_ - N_;     src = f1 + r * D_;   dst = &g_nf1[r];
    } else if (gid < B_ + 3 * N_) {
        int r = gid - B_ - 2 * N_; src = f2 + r * D_;   dst = &g_nf2[r];
    } else return;
    float s = 0.f;
    const float4* p = reinterpret_cast<const float4*>(src);
#pragma unroll
    for (int i = 0; i < 16; i++) {
        float4 v = p[i];
        s += v.x * v.x + v.y * v.y + v.z * v.z + v.w * v.w;
    }
    *dst = s;
}

// ---------------- K0b: fp16 x (natural) + star/f1/f2 (permuted) --------------
__global__ void k_h1(const float* __restrict__ x, const float* __restrict__ star,
                     const float* __restrict__ f1, const float* __restrict__ f2) {
    int gid = blockIdx.x * blockDim.x + threadIdx.x;
    if (gid < B_ * D_) {
        ((__half*)g_xh)[gid] = __float2half(x[gid]);
        return;
    }
    gid -= B_ * D_;
    if (gid >= 3 * NP * D_) return;
    int which = gid / (NP * D_);
    int rem = gid - which * (NP * D_);
    int i = rem >> 6, d = rem & 63;     // d = storage index
    int dp = physpos(d);
    float v = 0.f;
    if (i < N_) {
        const float* src = (which == 0) ? star : ((which == 1) ? f1 : f2);
        v = src[(long)i * D_ + dp];
    }
    __half hv = __float2half(v);
    if (which == 0) g_sth[i][d] = hv;
    else if (which == 1) g_f1h[i][d] = hv;
    else g_f2h[i][d] = hv;
}

// ---------------- K0c: fp16 fcomb (smem tile transpose, i-permuted write) ----
__global__ void k_h2(const float* __restrict__ f1, const float* __restrict__ f2) {
    __shared__ float ts[32][33];
    int tx = threadIdx.x, ty = threadIdx.y;
    int i0 = blockIdx.x * 32;
    int by = blockIdx.y;
    int i = i0 + tx;                     // physical i (coalesced reads)
    int ic = i0 + istor(tx);             // storage column (write)
    float sc = (i < N_) ? __expf(-g_ns[i]) : 0.f;
    if (by == 4) {
        for (int r = 128 + ty; r < FC_ROWS; r += 8)
            g_fch[r][ic] = __float2half((r == 128) ? sc : 0.f);
        return;
    }
    const float* src = (by < 2) ? f1 : f2;
    int d0 = (by & 1) * 32;
    int rowbase = by * 32;
#pragma unroll
    for (int q = 0; q < 4; q++) {
        int r = ty + q * 8;
        ts[r][tx] = src[(long)min(i0 + r, N_ - 1) * 64 + d0 + tx];
    }
    __syncthreads();
#pragma unroll
    for (int q = 0; q < 4; q++) {
        int d = ty + q * 8;
        g_fch[rowbase + d][ic] = __float2half((i < N_) ? ts[tx][d] * sc : 0.f);
    }
}

// ---------------- K0d: fp16 slbcomb (smem tile transpose, i-permuted write) --
__global__ void k_h3(const float* __restrict__ slb) {
    __shared__ float ts[32][33];
    int tx = threadIdx.x, ty = threadIdx.y;
    int i0 = blockIdx.x * 32;
    int br = blockIdx.z;
    int i = i0 + tx;
    int ic = i0 + istor(tx);
    float sc = (i < N_) ? __expf(-(br ? g_nf2[i] : g_nf1[i])) : 0.f;
#pragma unroll
    for (int q = 0; q < 4; q++) {
        int r = ty + q * 8;
        ts[r][tx] = slb[(long)min(i0 + r, N_ - 1) * 32 + tx];
    }
    __syncthreads();
#pragma unroll
    for (int q = 0; q < 4; q++) {
        int d = ty + q * 8;
        g_slh[br][d][ic] = __float2half((i < N_) ? ts[tx][d] * sc : 0.f);
    }
    if (ty == 0) g_slh[br][32][ic] = __float2half(sc);
    for (int r = 33 + ty; r < SL_ROWS; r += 8) g_slh[br][r][ic] = __float2half(0.f);
}

// ---------------- phase A ----------------------------------------------------
// 128 threads (4 warps, JT=64), 2 CTAs/SM, CH=128, fp16 operands, ex2.f16x2 exp.
// All exp domain pre-scaled by log2(e): t_l = S*2L2E - nx*L2E ; e = ex2(t_l).
// smem (bytes): ST 20480 | FC 39168 | NS 512 = 60160
#define SA_ST 0
#define SA_FC 20480
#define SA_NS 59648
#define SA_SIZE 60160

__global__ __launch_bounds__(128, 2)
void k_phaseA() {
    extern __shared__ char smem[];
    uint32_t* STu = (uint32_t*)(smem + SA_ST);
    uint32_t* FCu = (uint32_t*)(smem + SA_FC);
    float* nsb = (float*)(smem + SA_NS);   // [128], pre-scaled by L2E
    const uint32_t STb = su32(STu), FCb = su32(FCu);

    const int tid = threadIdx.x;
    const int w = tid >> 5, lane = tid & 31;
    const int r0 = lane >> 2, c0l = lane & 3;
    const int jw = w * 16;
    const int j0 = blockIdx.x * 64;
    const int slab = blockIdx.y;
    const int ch0 = slab * CPS_A;
    const int ch1 = min(ch0 + CPS_A, NCH_TOT);
    const int nc = ch1 - ch0;

    // A-fragments from g_xh (natural pairs: pair p at u32 slot p)
    uint32_t aF[4][4];
    {
        const uint32_t* xr0 = (const uint32_t*)&g_xh[j0 + jw + r0][0];
        const uint32_t* xr1 = (const uint32_t*)&g_xh[j0 + jw + r0 + 8][0];
#pragma unroll
        for (int ks = 0; ks < 4; ks++) {
            aF[ks][0] = xr0[ks * 8 + c0l];
            aF[ks][1] = xr1[ks * 8 + c0l];
            aF[ks][2] = xr0[ks * 8 + c0l + 4];
            aF[ks][3] = xr1[ks * 8 + c0l + 4];
        }
    }
    const float nx0 = g_nx[j0 + jw + r0] * L2E_;
    const float nx1 = g_nx[j0 + jw + r0 + 8] * L2E_;

    // chunk 0 loads
    {
        const int i0p = ch0 * 128;
        for (int idx = tid; idx < 128 * 8; idx += 128) {
            int r = idx >> 3, g = idx & 7;
            long gi = min(i0p + r, N_ - 1);
            CPA16(STb + r * 160 + g * 16, (const char*)&g_sth[gi][0] + g * 16);
        }
        for (int idx = tid; idx < FC_ROWS * 16; idx += 128) {
            int r = idx >> 4, g = idx & 15;
            CPA16(FCb + r * 288 + g * 16, (const char*)&g_fch[r][i0p] + g * 16);
        }
        { int gi = i0p + tid; nsb[tid] = (gi < N_) ? g_ns[gi] * L2E_ : 1e30f; }
        CP_COMMIT(); CP_WAIT0();
        __syncthreads();
    }

    float acc[17][4];
#pragma unroll
    for (int n = 0; n < 17; n++)
#pragma unroll
        for (int q = 0; q < 4; q++) acc[n][q] = 0.f;

    for (int c = 0; c < nc; c++) {
        const int i0 = (ch0 + c) * 128;

        // fused per kc (16 i's): MMA1 (nt=2kc,2kc+1) -> ex2 -> MMA2(kc)
#pragma unroll
        for (int kc = 0; kc < 8; kc++) {
            float cf0[4] = {0.f, 0.f, 0.f, 0.f};
            float cf1[4] = {0.f, 0.f, 0.f, 0.f};
#pragma unroll
            for (int ks = 0; ks < 4; ks++) {
                uint2 q0 = *(const uint2*)&STu[((2 * kc) * 8 + r0) * ST_STR + ks * 8 + 2 * c0l];
                uint32_t b0[2] = {q0.x, q0.y};
                mma16(cf0, aF[ks], b0);
                uint2 q1 = *(const uint2*)&STu[((2 * kc + 1) * 8 + r0) * ST_STR + ks * 8 + 2 * c0l];
                uint32_t b1[2] = {q1.x, q1.y};
                mma16(cf1, aF[ks], b1);
            }
            const int ic0 = kc * 16 + 2 * c0l, ic1 = ic0 + 1;
            const int jc0 = ic0 + 8, jc1 = ic1 + 8;
            float ns0 = nsb[ic0], ns1 = nsb[ic1];
            float ns2 = nsb[jc0], ns3 = nsb[jc1];
            float t00 = fmaf(cf0[0], TWO_L2E_, -nx0), t01 = fmaf(cf0[1], TWO_L2E_, -nx0);
            float t10 = fmaf(cf0[2], TWO_L2E_, -nx1), t11 = fmaf(cf0[3], TWO_L2E_, -nx1);
            float t20 = fmaf(cf1[0], TWO_L2E_, -nx0), t21 = fmaf(cf1[1], TWO_L2E_, -nx0);
            float t30 = fmaf(cf1[2], TWO_L2E_, -nx1), t31 = fmaf(cf1[3], TWO_L2E_, -nx1);
            if (t00 >= ns0) atomicMin(&g_match[j0 + jw + r0], i0 + ic0);
            if (t01 >= ns1) atomicMin(&g_match[j0 + jw + r0], i0 + ic1);
            if (t10 >= ns0) atomicMin(&g_match[j0 + jw + r0 + 8], i0 + ic0);
            if (t11 >= ns1) atomicMin(&g_match[j0 + jw + r0 + 8], i0 + ic1);
            if (t20 >= ns2) atomicMin(&g_match[j0 + jw + r0], i0 + jc0);
            if (t21 >= ns3) atomicMin(&g_match[j0 + jw + r0], i0 + jc1);
            if (t30 >= ns2) atomicMin(&g_match[j0 + jw + r0 + 8], i0 + jc0);
            if (t31 >= ns3) atomicMin(&g_match[j0 + jw + r0 + 8], i0 + jc1);
            uint32_t a2[4];
            a2[0] = ex2h2(t00, t01);
            a2[1] = ex2h2(t10, t11);
            a2[2] = ex2h2(t20, t21);
            a2[3] = ex2h2(t30, t31);
#pragma unroll
            for (int nt2 = 0; nt2 < 17; nt2++) {
                uint2 q = *(const uint2*)&FCu[(nt2 * 8 + r0) * FC_STR + kc * 8 + 2 * c0l];
                uint32_t b[2] = {q.x, q.y};
                mma16(acc[nt2], a2, b);
            }
        }

        // reload (cross-CTA overlap hides this)
        if (c + 1 < nc) {
            __syncthreads();
            const int i0n = i0 + 128;
            for (int idx = tid; idx < 128 * 8; idx += 128) {
                int r = idx >> 3, g = idx & 7;
                long gi = min(i0n + r, N_ - 1);
                CPA16(STb + r * 160 + g * 16, (const char*)&g_sth[gi][0] + g * 16);
            }
            for (int idx = tid; idx < FC_ROWS * 16; idx += 128) {
                int r = idx >> 4, g = idx & 15;
                CPA16(FCb + r * 288 + g * 16, (const char*)&g_fch[r][i0n] + g * 16);
            }
            { int gi = i0n + tid; nsb[tid] = (gi < N_) ? g_ns[gi] * L2E_ : 1e30f; }
            CP_COMMIT(); CP_WAIT0();
            __syncthreads();
        }
    }

    // writeback
    const int jr0 = j0 + jw + r0, jr1 = jr0 + 8;
#pragma unroll
    for (int nt = 0; nt < 17; nt++) {
        int n = nt * 8 + 2 * c0l;
        if (n < 64) {
            *(float2*)&g_acc1_part[slab][jr0][n] = make_float2(acc[nt][0], acc[nt][1]);
            *(float2*)&g_acc1_part[slab][jr1][n] = make_float2(acc[nt][2], acc[nt][3]);
        } else if (n < 128) {
            *(float2*)&g_acc2_part[slab][jr0][n - 64] = make_float2(acc[nt][0], acc[nt][1]);
            *(float2*)&g_acc2_part[slab][jr1][n - 64] = make_float2(acc[nt][2], acc[nt][3]);
        } else if (n == 128) {
            g_esum_part[slab][jr0] = acc[nt][0];
            g_esum_part[slab][jr1] = acc[nt][2];
        }
    }
}

// ---------------- K2: middle — xt, y = xt@W+b, argmin label ------------------
__global__ __launch_bounds__(128)
void k_mid(const float* __restrict__ f1, const float* __restrict__ f2,
           const float* __restrict__ W1, const float* __restrict__ b1,
           const float* __restrict__ W2, const float* __restrict__ b2,
           const float* __restrict__ u1, const float* __restrict__ u2) {
    int j = blockIdx.x;
    int t = threadIdx.x;

    __shared__ float xts[D_];
    __shared__ float ys[DY_];
    __shared__ float esum_s;
    __shared__ float ny_s;
    __shared__ float redv[128];
    __shared__ int   redi[128];

    int  mi = g_match[j];
    bool hm = (mi != 0x7fffffff);
    if (t == 0) {
        float s = 0.f;
        for (int k = 0; k < NSLAB_A; k++) s += g_esum_part[k][j];
        esum_s = s;
    }
    __syncthreads();

    for (int br = 0; br < 2; br++) {
        const float* f  = br ? f2 : f1;
        const float* W  = br ? W2 : W1;
        const float* bb = br ? b2 : b1;
        const float* u  = br ? u2 : u1;

        if (t < D_) {
            float a = 0.f;
            if (br) { for (int k = 0; k < NSLAB_A; k++) a += g_acc2_part[k][j][t]; }
            else    { for (int k = 0; k < NSLAB_A; k++) a += g_acc1_part[k][j][t]; }
            float v = hm ? f[mi * D_ + t] : a / esum_s;
            xts[t] = v;
            if (br) g_xt2[j][t] = v; else g_xt1[j][t] = v;
            g_xth[br][j][t] = __float2half(v);
        }
        __syncthreads();
        if (t == 0) {
            float s = 0.f;
            for (int d = 0; d < D_; d++) s += xts[d] * xts[d];
            if (br) g_nxt2[j] = s; else g_nxt1[j] = s;
        }
        if (t < DY_) {
            float a = bb[t];
            for (int d = 0; d < D_; d++) a += xts[d] * W[d * DY_ + t];
            ys[t] = a;
        }
        __syncthreads();
        if (t == 0) {
            float s = 0.f;
            for (int dy = 0; dy < DY_; dy++) s += ys[dy] * ys[dy];
            ny_s = s;
        }
        __syncthreads();

        float v = FLT_MAX;
        int   vi = 0x7fffffff;
        if (t < L_) {
            float nu = 0.f, dot = 0.f;
            for (int dy = 0; dy < DY_; dy++) {
                float uu = u[t * DY_ + dy];
                nu += uu * uu;
                dot += uu * ys[dy];
            }
            v = fmaxf(ny_s + nu - 2.f * dot, 0.f);
            vi = t;
        }
        redv[t] = v; redi[t] = vi;
        __syncthreads();
        for (int off = 64; off > 0; off >>= 1) {
            if (t < off) {
                float v2 = redv[t + off]; int i2 = redi[t + off];
                if (v2 < redv[t] || (v2 == redv[t] && i2 < redi[t])) {
                    redv[t] = v2; redi[t] = i2;
                }
            }
            __syncthreads();
        }
        if (t == 0) { if (br) g_yidx2[j] = redi[0]; else g_yidx1[j] = redi[0]; }
        __syncthreads();
    }
}

// ---------------- phase C ----------------------------------------------------
// fp16 operands + ex2.f16x2 with folded log2 label-multiplier:
// e*m = ex2(S*2L2E - nxt*L2E + lmt), lmt = -eta*L2E*ld.
// smem (bytes): F 20480 | SL 11520 | MT 25856 | LI 512 | YJ 256 = 58624
#define SC_F  0
#define SC_SL 20480
#define SC_MT 32000
#define SC_LI 57856
#define SC_YJ 58368
#define SC_SIZE 58624

__global__ __launch_bounds__(128, 2)
void k_phaseC(const float* __restrict__ ld1, const float* __restrict__ ld2,
              const int* __restrict__ li1, const int* __restrict__ li2) {
    extern __shared__ char smem[];
    uint32_t* Fu  = (uint32_t*)(smem + SC_F);
    uint32_t* SLu = (uint32_t*)(smem + SC_SL);
    float* mt  = (float*)(smem + SC_MT);    // [64][101] : lmt (log2-domain)
    int*   lib = (int*)(smem + SC_LI);      // [128]
    int*   yjs = (int*)(smem + SC_YJ);      // [64]
    const uint32_t Fb = su32(Fu), SLb = su32(SLu);

    const int tid = threadIdx.x;
    const int w = tid >> 5, lane = tid & 31;
    const int r0 = lane >> 2, c0l = lane & 3;
    const int jw = w * 16;
    const int j0 = blockIdx.x * 64;
    const int slab = blockIdx.y;
    const int br = blockIdx.z;
    const int ch0 = slab * CPS_C;
    const int ch1 = min(ch0 + CPS_C, NCH_TOT);
    const int nc = ch1 - ch0;

    const float* ld = br ? ld2 : ld1;
    const int*   li = br ? li2 : li1;
    const __half (*fh)[D_] = br ? g_f2h : g_f1h;
    const float* nxt = br ? g_nxt2 : g_nxt1;
    const int*   yix = br ? g_yidx2 : g_yidx1;
    float (*nump)[B_][DY_] = br ? g_num2_part : g_num1_part;
    float (*denp)[B_]      = br ? g_den2_part : g_den1_part;

    // A-fragments from g_xth (natural pairs)
    uint32_t aF[4][4];
    {
        const uint32_t* xr0 = (const uint32_t*)&g_xth[br][j0 + jw + r0][0];
        const uint32_t* xr1 = (const uint32_t*)&g_xth[br][j0 + jw + r0 + 8][0];
#pragma unroll
        for (int ks = 0; ks < 4; ks++) {
            aF[ks][0] = xr0[ks * 8 + c0l];
            aF[ks][1] = xr1[ks * 8 + c0l];
            aF[ks][2] = xr0[ks * 8 + c0l + 4];
            aF[ks][3] = xr1[ks * 8 + c0l + 4];
        }
    }
    const float nxt0 = nxt[j0 + jw + r0] * L2E_;
    const float nxt1 = nxt[j0 + jw + r0 + 8] * L2E_;
    if (tid < 64) yjs[tid] = yix[j0 + tid];
    __syncthreads();
    // lmt table: -eta*L2E*ld (no expf needed)
    for (int idx = tid; idx < 64 * L_; idx += 128) {
        int j = idx / L_, l = idx - j * L_;
        mt[j * 101 + l] = -(ETA_ * L2E_) * ld[l * L_ + yjs[j]];
    }

    // chunk 0 loads
    {
        const int i0p = ch0 * 128;
        for (int idx = tid; idx < 128 * 8; idx += 128) {
            int r = idx >> 3, g = idx & 7;
            long gi = min(i0p + r, N_ - 1);
            CPA16(Fb + r * 160 + g * 16, (const char*)&fh[gi][0] + g * 16);
        }
        for (int idx = tid; idx < SL_ROWS * 16; idx += 128) {
            int r = idx >> 4, g = idx & 15;
            CPA16(SLb + r * 288 + g * 16, (const char*)&g_slh[br][r][i0p] + g * 16);
        }
        lib[tid] = li[min(i0p + tid, N_ - 1)];
        CP_COMMIT(); CP_WAIT0();
        __syncthreads();
    }

    float acc[5][4];
#pragma unroll
    for (int n = 0; n < 5; n++)
#pragma unroll
        for (int q = 0; q < 4; q++) acc[n][q] = 0.f;

    for (int c = 0; c < nc; c++) {
#pragma unroll
        for (int kc = 0; kc < 8; kc++) {
            float cf0[4] = {0.f, 0.f, 0.f, 0.f};
            float cf1[4] = {0.f, 0.f, 0.f, 0.f};
#pragma unroll
            for (int ks = 0; ks < 4; ks++) {
                uint2 q0 = *(const uint2*)&Fu[((2 * kc) * 8 + r0) * ST_STR + ks * 8 + 2 * c0l];
                uint32_t b0[2] = {q0.x, q0.y};
                mma16(cf0, aF[ks], b0);
                uint2 q1 = *(const uint2*)&Fu[((2 * kc + 1) * 8 + r0) * ST_STR + ks * 8 + 2 * c0l];
                uint32_t b1[2] = {q1.x, q1.y};
                mma16(cf1, aF[ks], b1);
            }
            const int ic0 = kc * 16 + 2 * c0l, ic1 = ic0 + 1;
            const int jc0 = ic0 + 8, jc1 = ic1 + 8;
            int l0 = lib[ic0], l1 = lib[ic1];
            int l2 = lib[jc0], l3 = lib[jc1];
            float m00 = mt[(jw + r0) * 101 + l0], m01 = mt[(jw + r0) * 101 + l1];
            float m10 = mt[(jw + r0 + 8) * 101 + l0], m11 = mt[(jw + r0 + 8) * 101 + l1];
            float m20 = mt[(jw + r0) * 101 + l2], m21 = mt[(jw + r0) * 101 + l3];
            float m30 = mt[(jw + r0 + 8) * 101 + l2], m31 = mt[(jw + r0 + 8) * 101 + l3];
            uint32_t a2[4];
            a2[0] = ex2h2(fmaf(cf0[0], TWO_L2E_, -nxt0) + m00,
                          fmaf(cf0[1], TWO_L2E_, -nxt0) + m01);
            a2[1] = ex2h2(fmaf(cf0[2], TWO_L2E_, -nxt1) + m10,
                          fmaf(cf0[3], TWO_L2E_, -nxt1) + m11);
            a2[2] = ex2h2(fmaf(cf1[0], TWO_L2E_, -nxt0) + m20,
                          fmaf(cf1[1], TWO_L2E_, -nxt0) + m21);
            a2[3] = ex2h2(fmaf(cf1[2], TWO_L2E_, -nxt1) + m30,
                          fmaf(cf1[3], TWO_L2E_, -nxt1) + m31);
#pragma unroll
            for (int nt2 = 0; nt2 < 5; nt2++) {
                uint2 q = *(const uint2*)&SLu[(nt2 * 8 + r0) * SL_STR + kc * 8 + 2 * c0l];
                uint32_t b[2] = {q.x, q.y};
                mma16(acc[nt2], a2, b);
            }
        }

        if (c + 1 < nc) {
            __syncthreads();
            const int i0n = (ch0 + c + 1) * 128;
            for (int idx = tid; idx < 128 * 8; idx += 128) {
                int r = idx >> 3, g = idx & 7;
                long gi = min(i0n + r, N_ - 1);
                CPA16(Fb + r * 160 + g * 16, (const char*)&fh[gi][0] + g * 16);
            }
            for (int idx = tid; idx < SL_ROWS * 16; idx += 128) {
                int r = idx >> 4, g = idx & 15;
                CPA16(SLb + r * 288 + g * 16, (const char*)&g_slh[br][r][i0n] + g * 16);
            }
            lib[tid] = li[min(i0n + tid, N_ - 1)];
            CP_COMMIT(); CP_WAIT0();
            __syncthreads();
        }
    }

    const int jr0 = j0 + jw + r0, jr1 = jr0 + 8;
#pragma unroll
    for (int nt = 0; nt < 5; nt++) {
        int n = nt * 8 + 2 * c0l;
        if (n < 32) {
            *(float2*)&nump[slab][jr0][n] = make_float2(acc[nt][0], acc[nt][1]);
            *(float2*)&nump[slab][jr1][n] = make_float2(acc[nt][2], acc[nt][3]);
        } else if (n == 32) {
            denp[slab][jr0] = acc[nt][0];
            denp[slab][jr1] = acc[nt][2];
        }
    }
}

// ---------------- K4: reduce partials ----------------------------------------
__global__ void k_out(float* __restrict__ out) {
    int gid = blockIdx.x * blockDim.x + threadIdx.x;
    if (gid >= B_ * DY_) return;
    int j = gid >> 5, dy = gid & 31;
    float n1 = 0.f, d1 = 0.f, n2 = 0.f, d2 = 0.f;
    for (int s = 0; s < NSLAB_C; s++) {
        n1 += g_num1_part[s][j][dy];
        d1 += g_den1_part[s][j];
        n2 += g_num2_part[s][j][dy];
        d2 += g_den2_part[s][j];
    }
    out[gid] = 0.5f * (n1 / d1 + n2 / d2);
}

// ---------------- launch -----------------------------------------------------
extern "C" void kernel_launch(void* const* d_in, const int* in_sizes, int n_in,
                              void* d_out, int out_size) {
    const float* x    = (const float*)d_in[0];
    const float* star = (const float*)d_in[1];
    const float* slb  = (const float*)d_in[2];
    const float* f1   = (const float*)d_in[3];
    const float* f2   = (const float*)d_in[4];
    const float* u1   = (const float*)d_in[5];
    const float* u2   = (const float*)d_in[6];
    const float* ld1  = (const float*)d_in[7];
    const float* ld2  = (const float*)d_in[8];
    const float* W1   = (const float*)d_in[9];
    const float* b1   = (const float*)d_in[10];
    const float* W2   = (const float*)d_in[11];
    const float* b2   = (const float*)d_in[12];
    const int*   li1  = (const int*)d_in[13];
    const int*   li2  = (const int*)d_in[14];
    float* out = (float*)d_out;

    cudaFuncSetAttribute(k_phaseA, cudaFuncAttributeMaxDynamicSharedMemorySize, SA_SIZE);
    cudaFuncSetAttribute(k_phaseC, cudaFuncAttributeMaxDynamicSharedMemorySize, SC_SIZE);

    k_prep<<<(B_ + 3 * N_ + 255) / 256, 256>>>(x, star, f1, f2);
    k_h1<<<((B_ + 3 * NP) * D_ + 255) / 256, 256>>>(x, star, f1, f2);
    k_h2<<<dim3(NP / 32, 5), dim3(32, 8)>>>(f1, f2);
    k_h3<<<dim3(NP / 32, 1, 2), dim3(32, 8)>>>(slb);
    k_phaseA<<<dim3(32, NSLAB_A), 128, SA_SIZE>>>();
    k_mid<<<B_, 128>>>(f1, f2, W1, b1, W2, b2, u1, u2);
    k_phaseC<<<dim3(32, NSLAB_C, 2), 128, SC_SIZE>>>(ld1, ld2, li1, li2);
    k_out<<<(B_ * DY_ + 255) / 256, 256>>>(out);
}